// round 9
// baseline (speedup 1.0000x reference)
#include <cuda_runtime.h>
#include <cuda_bf16.h>
#include <math.h>
#include <stdint.h>

// ---------------------------------------------------------------------------
// BERT-base forward (B=128, S=64, D=768, H=12, L=12, FF=3072).
// GEMMs: mma.sync (HMMA) bf16 split hi/lo 3-pass, fp32 register accumulators.
// Split production fused into all producer epilogues (no cvt kernels).
// Attention / LayerNorm / embedding: fp32 CUDA-core kernels.
// ---------------------------------------------------------------------------

#define B_    128
#define S_    64
#define D_    768
#define H_    12
#define DK_   64
#define FF_   3072
#define L_    12
#define NT_   (B_ * S_)          // 8192 tokens

// -------------------- scratch (device globals; no allocs) -------------------
__device__ float g_h   [NT_ * D_];
__device__ float g_h1  [NT_ * D_];
__device__ float g_q   [NT_ * D_];
__device__ float g_k   [NT_ * D_];
__device__ float g_v   [NT_ * D_];
__device__ float g_tmp [NT_ * D_];
__device__ float g_probs[B_ * H_ * S_ * S_];
__device__ float g_pe  [S_ * D_];

// bf16 split activations: pairA (FF-sized, FF1 out), pairB (D-sized, h/ctx/h1)
__device__ __nv_bfloat16 g_ah[NT_ * FF_];
__device__ __nv_bfloat16 g_al[NT_ * FF_];
__device__ __nv_bfloat16 g_sh[NT_ * D_];
__device__ __nv_bfloat16 g_sl[NT_ * D_];

// bf16 split transposed weights: [L][N][K] layout (K contiguous per row)
__device__ __nv_bfloat16 g_wqh[L_ * D_ * D_];
__device__ __nv_bfloat16 g_wql[L_ * D_ * D_];
__device__ __nv_bfloat16 g_wkh[L_ * D_ * D_];
__device__ __nv_bfloat16 g_wkl[L_ * D_ * D_];
__device__ __nv_bfloat16 g_wvh[L_ * D_ * D_];
__device__ __nv_bfloat16 g_wvl[L_ * D_ * D_];
__device__ __nv_bfloat16 g_woh[L_ * D_ * D_];
__device__ __nv_bfloat16 g_wol[L_ * D_ * D_];
__device__ __nv_bfloat16 g_w1h[L_ * FF_ * D_];   // [L][3072][768]
__device__ __nv_bfloat16 g_w1l[L_ * FF_ * D_];
__device__ __nv_bfloat16 g_w2h[L_ * D_ * FF_];   // [L][768][3072]
__device__ __nv_bfloat16 g_w2l[L_ * D_ * FF_];

// -------------------- PTX helpers (all arch-agnostic, sm_80+) ---------------
__device__ __forceinline__ uint32_t smem_u32(const void* p) {
    uint32_t a;
    asm("{ .reg .u64 t; cvta.to.shared.u64 t, %1; cvt.u32.u64 %0, t; }"
        : "=r"(a) : "l"(p));
    return a;
}
__device__ __forceinline__ void cp16(uint32_t s, const void* g) {
    asm volatile("cp.async.cg.shared.global [%0], [%1], 16;" :: "r"(s), "l"(g) : "memory");
}
__device__ __forceinline__ void ldsm4(uint32_t& r0, uint32_t& r1, uint32_t& r2,
                                      uint32_t& r3, uint32_t a) {
    asm volatile("ldmatrix.sync.aligned.m8n8.x4.shared.b16 {%0,%1,%2,%3}, [%4];"
                 : "=r"(r0), "=r"(r1), "=r"(r2), "=r"(r3) : "r"(a));
}
__device__ __forceinline__ void mma16816(float* c, const uint32_t* a,
                                         uint32_t b0, uint32_t b1) {
    asm volatile("mma.sync.aligned.m16n8k16.row.col.f32.bf16.bf16.f32 "
                 "{%0,%1,%2,%3}, {%4,%5,%6,%7}, {%8,%9}, {%0,%1,%2,%3};"
                 : "+f"(c[0]), "+f"(c[1]), "+f"(c[2]), "+f"(c[3])
                 : "r"(a[0]), "r"(a[1]), "r"(a[2]), "r"(a[3]), "r"(b0), "r"(b1));
}

// -------------------- HMMA split-bf16 GEMM ----------------------------------
// C[8192, N] = A[8192, K] @ W[K, N] + bias (+GELU). A/W pre-split hi/lo bf16,
// W pre-transposed to Bt[N, K]. CTA tile 128x256, BK=64, 3 passes per chunk.
// 512 threads = 16 warps (4 M-quads x 4 N-quads), 2-stage cp.async pipeline.
// Output: fp32 (op.c) and/or bf16 hi/lo splits (op.oh/op.ol).
struct BOp { const __nv_bfloat16* bh; const __nv_bfloat16* bl;
             const float* bias; float* c;
             __nv_bfloat16* oh; __nv_bfloat16* ol; };

#define GT_       512
#define BM_       128
#define BN_       256
#define BK_       64
#define ATILE_    16384u       // 128 rows x 128 B
#define BTILE_    32768u       // 256 rows x 128 B
#define STAGE_B_  98304u       // Ah + Al + Bh + Bl
#define GSMEM_    (2 * 98304)

template <bool GELU>
__global__ __launch_bounds__(GT_, 1)
void gemm_kernel(const __nv_bfloat16* __restrict__ Ah,
                 const __nv_bfloat16* __restrict__ Al,
                 BOp op0, BOp op1, BOp op2, int K, int N)
{
    extern __shared__ char smem[];
    const uint32_t sb = smem_u32(smem);
    const int tid = threadIdx.x, wid = tid >> 5, l = tid & 31;
    const int wm = wid & 3;          // 4 warps along M (32 rows each)
    const int wn = wid >> 2;         // 4 warps along N (64 cols each)
    const BOp op = (blockIdx.z == 0) ? op0 : ((blockIdx.z == 1) ? op1 : op2);
    const int m0 = blockIdx.y * BM_;
    const int n0 = blockIdx.x * BN_;

    // per-lane ldmatrix addressing components
    const uint32_t swz  = (uint32_t)((l & 7) << 4);
    const int aRow0     = wm * 32 + ((l >> 3) & 1) * 8 + (l & 7);
    const uint32_t aSel = (uint32_t)(((l >> 4) & 1) * 16);
    const int bRow0     = wn * 64 + ((l >> 4) & 1) * 8 + (l & 7);
    const uint32_t bSel = (uint32_t)(((l >> 3) & 1) * 16);

    float acc[2][8][4];
    #pragma unroll
    for (int i = 0; i < 2; ++i)
        #pragma unroll
        for (int j = 0; j < 8; ++j)
            #pragma unroll
            for (int e = 0; e < 4; ++e) acc[i][j][e] = 0.0f;

    const int nch = K / BK_;

    // ---- async prefetch of one stage (Ah|Al|Bh|Bl tiles), 12 x cp16/thread --
    auto prefetch = [&](int c, int s) {
        const int kc = c * BK_;
        const uint32_t sbase = sb + (uint32_t)s * STAGE_B_;
        #pragma unroll
        for (int it = 0; it < 12; ++it) {
            const int g = tid + it * GT_;          // 0..6143
            const __nv_bfloat16* srcb;
            uint32_t toff;
            int row, seg;
            if (it < 4) {                           // A tiles: g in [0,2048)
                const int idx = g & 1023;
                row = idx >> 3; seg = idx & 7;
                const bool hi = (g < 1024);
                toff = hi ? 0u : ATILE_;
                srcb = (hi ? Ah : Al) + (size_t)(m0 + row) * K + kc + seg * 8;
            } else {                                // B tiles: gb in [0,4096)
                const int gb = g - 2048;
                const int idx = gb & 2047;
                row = idx >> 3; seg = idx & 7;
                const bool hi = (gb < 2048);
                toff = hi ? (2u * ATILE_) : (2u * ATILE_ + BTILE_);
                srcb = (hi ? op.bh : op.bl) + (size_t)(n0 + row) * K + kc + seg * 8;
            }
            const uint32_t sw = ((uint32_t)(seg * 16)) ^ ((uint32_t)(row & 7) << 4);
            cp16(sbase + toff + (uint32_t)row * 128 + sw, srcb);
        }
        asm volatile("cp.async.commit_group;" ::: "memory");
    };

    prefetch(0, 0);

    for (int c = 0; c < nch; ++c) {
        if (c + 1 < nch) {
            prefetch(c + 1, (c + 1) & 1);
            asm volatile("cp.async.wait_group 1;" ::: "memory");
        } else {
            asm volatile("cp.async.wait_group 0;" ::: "memory");
        }
        __syncthreads();

        const uint32_t sbase = sb + (uint32_t)(c & 1) * STAGE_B_;
        #pragma unroll
        for (int p = 0; p < 3; ++p) {
            const uint32_t Ab = sbase + (p == 2 ? ATILE_ : 0u);
            const uint32_t Bb = sbase + 2u * ATILE_ + (p == 1 ? BTILE_ : 0u);
            #pragma unroll
            for (int ks = 0; ks < 4; ++ks) {
                const uint32_t aCol = ((uint32_t)(ks * 32) + aSel) ^ swz;
                const uint32_t bCol = ((uint32_t)(ks * 32) + bSel) ^ swz;
                uint32_t a[2][4];
                #pragma unroll
                for (int mb = 0; mb < 2; ++mb)
                    ldsm4(a[mb][0], a[mb][1], a[mb][2], a[mb][3],
                          Ab + (uint32_t)(aRow0 + mb * 16) * 128 + aCol);
                #pragma unroll
                for (int nb = 0; nb < 4; ++nb) {
                    uint32_t b0, b1, b2, b3;
                    ldsm4(b0, b1, b2, b3,
                          Bb + (uint32_t)(bRow0 + nb * 16) * 128 + bCol);
                    #pragma unroll
                    for (int mb = 0; mb < 2; ++mb) {
                        mma16816(acc[mb][nb * 2 + 0], a[mb], b0, b1);
                        mma16816(acc[mb][nb * 2 + 1], a[mb], b2, b3);
                    }
                }
            }
        }
        __syncthreads();
    }

    // ---- epilogue: bias (+GELU), fp32 and/or bf16-split stores ----
    const int rbase = m0 + wm * 32 + (l >> 2);
    const int cbase = n0 + wn * 64 + (l & 3) * 2;
    #pragma unroll
    for (int mb = 0; mb < 2; ++mb) {
        #pragma unroll
        for (int nblk = 0; nblk < 8; ++nblk) {
            const int col = cbase + nblk * 8;
            const float bx = op.bias[col], by = op.bias[col + 1];
            float v[4] = { acc[mb][nblk][0] + bx, acc[mb][nblk][1] + by,
                           acc[mb][nblk][2] + bx, acc[mb][nblk][3] + by };
            if (GELU) {
                #pragma unroll
                for (int e = 0; e < 4; ++e)
                    v[e] = 0.5f * v[e] * (1.0f + erff(v[e] * 0.70710678118654752440f));
            }
            const int row = rbase + mb * 16;
            if (op.c) {
                float2 lo; lo.x = v[0]; lo.y = v[1];
                float2 hi; hi.x = v[2]; hi.y = v[3];
                *(float2*)(op.c + (size_t)row * N + col)       = lo;
                *(float2*)(op.c + (size_t)(row + 8) * N + col) = hi;
            }
            if (op.oh) {
                __nv_bfloat162 h0, l0, h1, l1;
                h0.x = __float2bfloat16(v[0]);
                h0.y = __float2bfloat16(v[1]);
                l0.x = __float2bfloat16(v[0] - __bfloat162float(h0.x));
                l0.y = __float2bfloat16(v[1] - __bfloat162float(h0.y));
                h1.x = __float2bfloat16(v[2]);
                h1.y = __float2bfloat16(v[3]);
                l1.x = __float2bfloat16(v[2] - __bfloat162float(h1.x));
                l1.y = __float2bfloat16(v[3] - __bfloat162float(h1.y));
                *(__nv_bfloat162*)(op.oh + (size_t)row * N + col)       = h0;
                *(__nv_bfloat162*)(op.ol + (size_t)row * N + col)       = l0;
                *(__nv_bfloat162*)(op.oh + (size_t)(row + 8) * N + col) = h1;
                *(__nv_bfloat162*)(op.ol + (size_t)(row + 8) * N + col) = l1;
            }
        }
    }
}

// -------------------- weight transpose + split: W[K,N] -> Wt[N,K] -----------
__global__ void wtrans_kernel(const float* __restrict__ W,
                              __nv_bfloat16* __restrict__ th,
                              __nv_bfloat16* __restrict__ tl, int Kd, int Nd)
{
    __shared__ float t[32][33];
    const size_t lo_ = (size_t)blockIdx.z * Kd * Nd;
    const float* Wp = W + lo_;
    __nv_bfloat16* thp = th + lo_;
    __nv_bfloat16* tlp = tl + lo_;
    const int n0 = blockIdx.x * 32, k0 = blockIdx.y * 32;
    const int tx = threadIdx.x & 31, ty = threadIdx.x >> 5;

    #pragma unroll
    for (int j = 0; j < 32; j += 8)
        t[ty + j][tx] = Wp[(size_t)(k0 + ty + j) * Nd + n0 + tx];
    __syncthreads();
    #pragma unroll
    for (int j = 0; j < 32; j += 8) {
        const float v = t[tx][ty + j];
        const __nv_bfloat16 h = __float2bfloat16(v);
        const size_t o = (size_t)(n0 + ty + j) * Kd + k0 + tx;
        thp[o] = h;
        tlp[o] = __float2bfloat16(v - __bfloat162float(h));
    }
}

// fused transpose+split for the four DxD weight families (one launch)
struct W4 { const float* w; __nv_bfloat16* th; __nv_bfloat16* tl; };
__global__ void wtrans4_kernel(W4 a, W4 b, W4 c, W4 d)
{
    __shared__ float t[32][33];
    const int which = blockIdx.z & 3;
    const int lyr   = blockIdx.z >> 2;
    const W4 s = (which == 0) ? a : (which == 1) ? b : (which == 2) ? c : d;
    const size_t lo_ = (size_t)lyr * D_ * D_;
    const float* Wp = s.w + lo_;
    __nv_bfloat16* thp = s.th + lo_;
    __nv_bfloat16* tlp = s.tl + lo_;
    const int n0 = blockIdx.x * 32, k0 = blockIdx.y * 32;
    const int tx = threadIdx.x & 31, ty = threadIdx.x >> 5;

    #pragma unroll
    for (int j = 0; j < 32; j += 8)
        t[ty + j][tx] = Wp[(size_t)(k0 + ty + j) * D_ + n0 + tx];
    __syncthreads();
    #pragma unroll
    for (int j = 0; j < 32; j += 8) {
        const float v = t[tx][ty + j];
        const __nv_bfloat16 h = __float2bfloat16(v);
        const size_t o = (size_t)(n0 + ty + j) * D_ + k0 + tx;
        thp[o] = h;
        tlp[o] = __float2bfloat16(v - __bfloat162float(h));
    }
}

// -------------------- positional-encoding table -----------------------------
__global__ void pe_kernel(float* __restrict__ pe)
{
    const int s = blockIdx.x;
    for (int c = threadIdx.x; c < D_; c += blockDim.x) {
        const int j = c >> 1;
        const double e   = (double)(4 * j) / 768.0;
        const double inv = pow(10000.0, -e);
        const float  arg = (float)((double)s * inv);
        pe[s * D_ + c] = (c & 1) ? cosf(arg) : sinf(arg);
    }
}

// -------------------- embedding (fp32 + splits) -----------------------------
__global__ void embed_kernel(const int* __restrict__ x, const int* __restrict__ seg,
                             const float* __restrict__ tok, const float* __restrict__ se,
                             const float* __restrict__ pe, float* __restrict__ h,
                             __nv_bfloat16* __restrict__ sh, __nv_bfloat16* __restrict__ sl)
{
    const int t   = blockIdx.x;
    const int tid = threadIdx.x;
    const int s   = t & (S_ - 1);
    const int xi  = x[t];
    const int si  = seg[t];
    const size_t base = (size_t)t * D_;
    #pragma unroll
    for (int u = 0; u < 3; ++u) {
        const int c = tid + u * 256;
        const float v = tok[(size_t)xi * D_ + c] + se[(size_t)si * D_ + c] + pe[s * D_ + c];
        h[base + c] = v;
        const __nv_bfloat16 hb = __float2bfloat16(v);
        sh[base + c] = hb;
        sl[base + c] = __float2bfloat16(v - __bfloat162float(hb));
    }
}

// -------------------- attention: scores + masked softmax --------------------
__global__ void attn_scores_kernel(const float* __restrict__ q, const float* __restrict__ k,
                                   const int* __restrict__ x, float* __restrict__ probs)
{
    __shared__ float Qs[S_ * 65];
    __shared__ float Ks[S_ * 65];
    __shared__ int   mk[S_];

    const int bh = blockIdx.x;
    const int b  = bh / H_;
    const int h  = bh % H_;
    const int tid = threadIdx.x;

    const float* qbase = q + (size_t)(b * S_) * D_ + h * DK_;
    const float* kbase = k + (size_t)(b * S_) * D_ + h * DK_;

    for (int idx = tid; idx < S_ * DK_; idx += 256) {
        const int r = idx >> 6, d = idx & 63;
        Qs[r * 65 + d] = qbase[(size_t)r * D_ + d];
        Ks[r * 65 + d] = kbase[(size_t)r * D_ + d];
    }
    if (tid < S_) mk[tid] = x[b * S_ + tid];
    __syncthreads();

    const int row = tid >> 2;
    const int jc  = (tid & 3) * 16;

    float sc[16];
    #pragma unroll
    for (int jj = 0; jj < 16; ++jj) sc[jj] = 0.0f;

    for (int d = 0; d < DK_; ++d) {
        const float qv = Qs[row * 65 + d];
        #pragma unroll
        for (int jj = 0; jj < 16; ++jj)
            sc[jj] += qv * Ks[(jc + jj) * 65 + d];
    }

    float mx = -3.0e38f;
    #pragma unroll
    for (int jj = 0; jj < 16; ++jj) {
        const float v = (mk[jc + jj] > 0) ? sc[jj] * 0.125f : -1.0e9f;
        sc[jj] = v;
        mx = fmaxf(mx, v);
    }
    mx = fmaxf(mx, __shfl_xor_sync(0xffffffffu, mx, 1));
    mx = fmaxf(mx, __shfl_xor_sync(0xffffffffu, mx, 2));

    float sum = 0.0f;
    #pragma unroll
    for (int jj = 0; jj < 16; ++jj) {
        sc[jj] = expf(sc[jj] - mx);
        sum += sc[jj];
    }
    sum += __shfl_xor_sync(0xffffffffu, sum, 1);
    sum += __shfl_xor_sync(0xffffffffu, sum, 2);
    const float inv = 1.0f / sum;

    float* outp = probs + (size_t)bh * (S_ * S_) + row * S_ + jc;
    #pragma unroll
    for (int jj = 0; jj < 16; ++jj) outp[jj] = sc[jj] * inv;
}

// -------------------- attention: ctx = P @ V (emit bf16 splits) -------------
__global__ void attn_ctx_kernel(const float* __restrict__ probs, const float* __restrict__ v,
                                __nv_bfloat16* __restrict__ oh, __nv_bfloat16* __restrict__ ol)
{
    __shared__ float Ps[S_ * 65];
    __shared__ float Vs[S_ * DK_];

    const int bh = blockIdx.x;
    const int b  = bh / H_;
    const int h  = bh % H_;
    const int tid = threadIdx.x;

    const float* pbase = probs + (size_t)bh * (S_ * S_);
    const float* vbase = v + (size_t)(b * S_) * D_ + h * DK_;

    for (int idx = tid; idx < S_ * S_; idx += 256)
        Ps[(idx >> 6) * 65 + (idx & 63)] = pbase[idx];
    for (int idx = tid; idx < S_ * DK_; idx += 256)
        Vs[idx] = vbase[(size_t)(idx >> 6) * D_ + (idx & 63)];
    __syncthreads();

    const int row = tid >> 2;
    const int d0  = (tid & 3) * 16;

    float acc[16];
    #pragma unroll
    for (int dd = 0; dd < 16; ++dd) acc[dd] = 0.0f;

    for (int j = 0; j < S_; ++j) {
        const float p = Ps[row * 65 + j];
        #pragma unroll
        for (int dd = 0; dd < 16; ++dd)
            acc[dd] += p * Vs[j * DK_ + d0 + dd];
    }

    const size_t obase = (size_t)(b * S_ + row) * D_ + h * DK_ + d0;
    #pragma unroll
    for (int dd = 0; dd < 16; dd += 2) {
        __nv_bfloat162 hb, lb;
        hb.x = __float2bfloat16(acc[dd]);
        hb.y = __float2bfloat16(acc[dd + 1]);
        lb.x = __float2bfloat16(acc[dd]     - __bfloat162float(hb.x));
        lb.y = __float2bfloat16(acc[dd + 1] - __bfloat162float(hb.y));
        *(__nv_bfloat162*)(oh + obase + dd) = hb;
        *(__nv_bfloat162*)(ol + obase + dd) = lb;
    }
}

// -------------------- residual add + layernorm (fp32 + splits) --------------
__global__ void resid_ln_kernel(const float* __restrict__ a, const float* __restrict__ r,
                                const float* __restrict__ g, const float* __restrict__ be,
                                float* __restrict__ out,
                                __nv_bfloat16* __restrict__ oh, __nv_bfloat16* __restrict__ ol)
{
    const int t   = blockIdx.x;
    const int tid = threadIdx.x;
    const size_t base = (size_t)t * D_;

    const float y0 = a[base + tid]       + r[base + tid];
    const float y1 = a[base + tid + 256] + r[base + tid + 256];
    const float y2 = a[base + tid + 512] + r[base + tid + 512];

    __shared__ float red[256];
    red[tid] = y0 + y1 + y2;
    __syncthreads();
    #pragma unroll
    for (int o = 128; o > 0; o >>= 1) {
        if (tid < o) red[tid] += red[tid + o];
        __syncthreads();
    }
    const float mu = red[0] * (1.0f / 768.0f);
    __syncthreads();

    const float d0 = y0 - mu, d1 = y1 - mu, d2 = y2 - mu;
    red[tid] = d0 * d0 + d1 * d1 + d2 * d2;
    __syncthreads();
    #pragma unroll
    for (int o = 128; o > 0; o >>= 1) {
        if (tid < o) red[tid] += red[tid + o];
        __syncthreads();
    }
    const float var = red[0] * (1.0f / 768.0f);
    const float inv = rsqrtf(var + 1e-5f);

    const float o0 = d0 * inv * g[tid]       + be[tid];
    const float o1 = d1 * inv * g[tid + 256] + be[tid + 256];
    const float o2 = d2 * inv * g[tid + 512] + be[tid + 512];
    out[base + tid]       = o0;
    out[base + tid + 256] = o1;
    out[base + tid + 512] = o2;

    const __nv_bfloat16 h0 = __float2bfloat16(o0);
    const __nv_bfloat16 h1 = __float2bfloat16(o1);
    const __nv_bfloat16 h2 = __float2bfloat16(o2);
    oh[base + tid]       = h0;
    oh[base + tid + 256] = h1;
    oh[base + tid + 512] = h2;
    ol[base + tid]       = __float2bfloat16(o0 - __bfloat162float(h0));
    ol[base + tid + 256] = __float2bfloat16(o1 - __bfloat162float(h1));
    ol[base + tid + 512] = __float2bfloat16(o2 - __bfloat162float(h2));
}

// ---------------------------------------------------------------------------
extern "C" void kernel_launch(void* const* d_in, const int* in_sizes, int n_in,
                              void* d_out, int out_size)
{
    const int*   x    = (const int*)  d_in[0];
    const int*   seg  = (const int*)  d_in[1];
    const float* tok  = (const float*)d_in[2];
    const float* se   = (const float*)d_in[3];
    const float* Wq   = (const float*)d_in[4];
    const float* bq   = (const float*)d_in[5];
    const float* Wk   = (const float*)d_in[6];
    const float* bk   = (const float*)d_in[7];
    const float* Wv   = (const float*)d_in[8];
    const float* bv   = (const float*)d_in[9];
    const float* Wo   = (const float*)d_in[10];
    const float* bo   = (const float*)d_in[11];
    const float* lng  = (const float*)d_in[12];
    const float* lnb  = (const float*)d_in[13];
    const float* W1   = (const float*)d_in[14];
    const float* b1   = (const float*)d_in[15];
    const float* W2   = (const float*)d_in[16];
    const float* b2   = (const float*)d_in[17];
    float* out = (float*)d_out;

    float *h, *h1, *q, *k, *v, *tmp, *probs, *pe;
    __nv_bfloat16 *ah, *al, *sh, *sl;
    __nv_bfloat16 *wqh, *wql, *wkh, *wkl, *wvh, *wvl, *woh, *wol, *w1h, *w1l, *w2h, *w2l;
    cudaGetSymbolAddress((void**)&h,     g_h);
    cudaGetSymbolAddress((void**)&h1,    g_h1);
    cudaGetSymbolAddress((void**)&q,     g_q);
    cudaGetSymbolAddress((void**)&k,     g_k);
    cudaGetSymbolAddress((void**)&v,     g_v);
    cudaGetSymbolAddress((void**)&tmp,   g_tmp);
    cudaGetSymbolAddress((void**)&probs, g_probs);
    cudaGetSymbolAddress((void**)&pe,    g_pe);
    cudaGetSymbolAddress((void**)&ah,    g_ah);
    cudaGetSymbolAddress((void**)&al,    g_al);
    cudaGetSymbolAddress((void**)&sh,    g_sh);
    cudaGetSymbolAddress((void**)&sl,    g_sl);
    cudaGetSymbolAddress((void**)&wqh,   g_wqh);
    cudaGetSymbolAddress((void**)&wql,   g_wql);
    cudaGetSymbolAddress((void**)&wkh,   g_wkh);
    cudaGetSymbolAddress((void**)&wkl,   g_wkl);
    cudaGetSymbolAddress((void**)&wvh,   g_wvh);
    cudaGetSymbolAddress((void**)&wvl,   g_wvl);
    cudaGetSymbolAddress((void**)&woh,   g_woh);
    cudaGetSymbolAddress((void**)&wol,   g_wol);
    cudaGetSymbolAddress((void**)&w1h,   g_w1h);
    cudaGetSymbolAddress((void**)&w1l,   g_w1l);
    cudaGetSymbolAddress((void**)&w2h,   g_w2h);
    cudaGetSymbolAddress((void**)&w2l,   g_w2l);

    cudaFuncSetAttribute(gemm_kernel<false>, cudaFuncAttributeMaxDynamicSharedMemorySize, GSMEM_);
    cudaFuncSetAttribute(gemm_kernel<true >, cudaFuncAttributeMaxDynamicSharedMemorySize, GSMEM_);

    // ---- setup: launches 0-4 (so that launch #5 = first QKV GEMM for ncu) --
    {
        W4 aq = { Wq, wqh, wql }, ak = { Wk, wkh, wkl };
        W4 av = { Wv, wvh, wvl }, ao = { Wo, woh, wol };
        wtrans4_kernel<<<dim3(24, 24, 4 * L_), 256>>>(aq, ak, av, ao);        // 0
    }
    wtrans_kernel<<<dim3(96, 24, L_), 256>>>(W1, w1h, w1l, D_, FF_);          // 1
    wtrans_kernel<<<dim3(24, 96, L_), 256>>>(W2, w2h, w2l, FF_, D_);          // 2
    pe_kernel<<<S_, 256>>>(pe);                                               // 3
    embed_kernel<<<NT_, 256>>>(x, seg, tok, se, pe, h, sh, sl);               // 4

    const dim3 gP(D_ / BN_, NT_ / BM_, 1);    // (3, 64)  N=768 GEMMs
    const dim3 gQKV(D_ / BN_, NT_ / BM_, 3);  // fused QKV
    const dim3 gF(FF_ / BN_, NT_ / BM_, 1);   // (12, 64) FF1

    for (int l = 0; l < L_; ++l) {
        const size_t wOff  = (size_t)l * D_ * D_;
        const size_t fOff1 = (size_t)l * D_ * FF_;
        const size_t fOff2 = (size_t)l * FF_ * D_;

        {   // QKV from h-splits (pairB)
            BOp oq = { wqh + wOff, wql + wOff, bq + l * D_, q,   nullptr, nullptr };
            BOp ok = { wkh + wOff, wkl + wOff, bk + l * D_, k,   nullptr, nullptr };
            BOp ov = { wvh + wOff, wvl + wOff, bv + l * D_, v,   nullptr, nullptr };
            gemm_kernel<false><<<gQKV, GT_, GSMEM_>>>(sh, sl, oq, ok, ov, D_, D_);
        }

        attn_scores_kernel<<<B_ * H_, 256>>>(q, k, x, probs);
        attn_ctx_kernel   <<<B_ * H_, 256>>>(probs, v, sh, sl);   // ctx splits -> pairB

        {   // O projection from ctx-splits
            BOp oo = { woh + wOff, wol + wOff, bo + l * D_, tmp, nullptr, nullptr };
            gemm_kernel<false><<<gP, GT_, GSMEM_>>>(sh, sl, oo, oo, oo, D_, D_);
        }
        resid_ln_kernel<<<NT_, 256>>>(tmp, h, lng + l * D_, lnb + l * D_, h1, sh, sl);

        {   // FF1 (+GELU) from h1-splits -> ff splits (pairA), no fp32 output
            BOp o1 = { w1h + fOff1, w1l + fOff1, b1 + l * FF_, nullptr, ah, al };
            gemm_kernel<true><<<gF, GT_, GSMEM_>>>(sh, sl, o1, o1, o1, D_, FF_);
        }
        {   // FF2 from ff-splits
            BOp o2 = { w2h + fOff2, w2l + fOff2, b2 + l * D_, tmp, nullptr, nullptr };
            gemm_kernel<false><<<gP, GT_, GSMEM_>>>(ah, al, o2, o2, o2, FF_, D_);
        }

        float* dst = (l == L_ - 1) ? out : h;
        resid_ln_kernel<<<NT_, 256>>>(tmp, h1, lng + l * D_, lnb + l * D_, dst, sh, sl);
    }
}

// round 11
// speedup vs baseline: 1.1846x; 1.1846x over previous
#include <cuda_runtime.h>
#include <cuda_bf16.h>
#include <math.h>
#include <stdint.h>

// ---------------------------------------------------------------------------
// BERT-base forward (B=128, S=64, D=768, H=12, L=12, FF=3072).
// GEMMs: mma.sync (HMMA) bf16 split hi/lo 3-pass, fp32 register accumulators.
// Round-8 proven GEMM geometry (256 thr, 128x128x64, 2-stage cp.async) +
// fused split-production epilogues (no cvt kernels) + fused attention.
// ---------------------------------------------------------------------------

#define B_    128
#define S_    64
#define D_    768
#define H_    12
#define DK_   64
#define FF_   3072
#define L_    12
#define NT_   (B_ * S_)          // 8192 tokens

// -------------------- scratch (device globals; no allocs) -------------------
__device__ float g_h   [NT_ * D_];
__device__ float g_h1  [NT_ * D_];
__device__ float g_q   [NT_ * D_];
__device__ float g_k   [NT_ * D_];
__device__ float g_v   [NT_ * D_];
__device__ float g_tmp [NT_ * D_];
__device__ float g_pe  [S_ * D_];

// bf16 split activations: pairA (FF-sized, FF1 out), pairB (D-sized, h/ctx/h1)
__device__ __nv_bfloat16 g_ah[NT_ * FF_];
__device__ __nv_bfloat16 g_al[NT_ * FF_];
__device__ __nv_bfloat16 g_sh[NT_ * D_];
__device__ __nv_bfloat16 g_sl[NT_ * D_];

// bf16 split transposed weights: [L][N][K] layout (K contiguous per row)
__device__ __nv_bfloat16 g_wqh[L_ * D_ * D_];
__device__ __nv_bfloat16 g_wql[L_ * D_ * D_];
__device__ __nv_bfloat16 g_wkh[L_ * D_ * D_];
__device__ __nv_bfloat16 g_wkl[L_ * D_ * D_];
__device__ __nv_bfloat16 g_wvh[L_ * D_ * D_];
__device__ __nv_bfloat16 g_wvl[L_ * D_ * D_];
__device__ __nv_bfloat16 g_woh[L_ * D_ * D_];
__device__ __nv_bfloat16 g_wol[L_ * D_ * D_];
__device__ __nv_bfloat16 g_w1h[L_ * FF_ * D_];   // [L][3072][768]
__device__ __nv_bfloat16 g_w1l[L_ * FF_ * D_];
__device__ __nv_bfloat16 g_w2h[L_ * D_ * FF_];   // [L][768][3072]
__device__ __nv_bfloat16 g_w2l[L_ * D_ * FF_];

// -------------------- PTX helpers (all arch-agnostic, sm_80+) ---------------
__device__ __forceinline__ uint32_t smem_u32(const void* p) {
    uint32_t a;
    asm("{ .reg .u64 t; cvta.to.shared.u64 t, %1; cvt.u32.u64 %0, t; }"
        : "=r"(a) : "l"(p));
    return a;
}
__device__ __forceinline__ void cp16(uint32_t s, const void* g) {
    asm volatile("cp.async.cg.shared.global [%0], [%1], 16;" :: "r"(s), "l"(g) : "memory");
}
__device__ __forceinline__ void ldsm4(uint32_t& r0, uint32_t& r1, uint32_t& r2,
                                      uint32_t& r3, uint32_t a) {
    asm volatile("ldmatrix.sync.aligned.m8n8.x4.shared.b16 {%0,%1,%2,%3}, [%4];"
                 : "=r"(r0), "=r"(r1), "=r"(r2), "=r"(r3) : "r"(a));
}
__device__ __forceinline__ void mma16816(float* c, const uint32_t* a,
                                         uint32_t b0, uint32_t b1) {
    asm volatile("mma.sync.aligned.m16n8k16.row.col.f32.bf16.bf16.f32 "
                 "{%0,%1,%2,%3}, {%4,%5,%6,%7}, {%8,%9}, {%0,%1,%2,%3};"
                 : "+f"(c[0]), "+f"(c[1]), "+f"(c[2]), "+f"(c[3])
                 : "r"(a[0]), "r"(a[1]), "r"(a[2]), "r"(a[3]), "r"(b0), "r"(b1));
}

// -------------------- HMMA split-bf16 GEMM (Round-8 geometry) ---------------
// C[8192, N] = A[8192, K] @ W[K, N] + bias (+GELU). A/W pre-split hi/lo bf16,
// W pre-transposed to Bt[N, K]. CTA tile 128x128, BK=64, 3 passes per chunk.
// Output: fp32 (op.c) and/or bf16 hi/lo splits (op.oh/op.ol).
struct BOp { const __nv_bfloat16* bh; const __nv_bfloat16* bl;
             const float* bias; float* c;
             __nv_bfloat16* oh; __nv_bfloat16* ol; };

#define GT_       256
#define BM_       128
#define BN_       128
#define BK_       64
#define TILE_B_   16384        // 128 rows x 128 bytes
#define STAGE_B_  65536        // Ah, Al, Bh, Bl
#define GSMEM_    (2 * STAGE_B_)

template <bool GELU>
__global__ __launch_bounds__(GT_, 1)
void gemm_kernel(const __nv_bfloat16* __restrict__ Ah,
                 const __nv_bfloat16* __restrict__ Al,
                 BOp op0, BOp op1, BOp op2, int K, int N)
{
    extern __shared__ char smem[];
    const uint32_t sb = smem_u32(smem);
    const int tid = threadIdx.x, wid = tid >> 5, l = tid & 31;
    const int wm = wid & 1;          // 2 warps along M
    const int wn = wid >> 1;         // 4 warps along N
    const BOp op = (blockIdx.z == 0) ? op0 : ((blockIdx.z == 1) ? op1 : op2);
    const int m0 = blockIdx.y * BM_;
    const int n0 = blockIdx.x * BN_;

    // per-lane ldmatrix addressing components
    const uint32_t swz    = (uint32_t)((l & 7) << 4);
    const int aRow0 = wm * 64 + ((l >> 3) & 1) * 8 + (l & 7);
    const uint32_t aSel   = (uint32_t)(((l >> 4) & 1) * 16);
    const int bRow0 = wn * 32 + ((l >> 4) & 1) * 8 + (l & 7);
    const uint32_t bSel   = (uint32_t)(((l >> 3) & 1) * 16);

    float acc[4][4][4];
    #pragma unroll
    for (int i = 0; i < 4; ++i)
        #pragma unroll
        for (int j = 0; j < 4; ++j)
            #pragma unroll
            for (int e = 0; e < 4; ++e) acc[i][j][e] = 0.0f;

    const int nch = K / BK_;

    // ---- async prefetch of one stage (Ah|Al|Bh|Bl tiles) ----
    auto prefetch = [&](int c, int s) {
        const int kc = c * BK_;
        const uint32_t sbase = sb + (uint32_t)s * STAGE_B_;
        #pragma unroll 4
        for (int g = tid; g < 4096; g += GT_) {
            const int t   = g >> 10;
            const int idx = g & 1023;
            const int row = idx >> 3, seg = idx & 7;
            const uint32_t bc = (uint32_t)(seg * 16);
            const uint32_t sa = sbase + (uint32_t)t * TILE_B_ + (uint32_t)row * 128
                              + (bc ^ ((uint32_t)(row & 7) << 4));
            const __nv_bfloat16* src;
            if      (t == 0) src = Ah    + (size_t)(m0 + row) * K + kc + seg * 8;
            else if (t == 1) src = Al    + (size_t)(m0 + row) * K + kc + seg * 8;
            else if (t == 2) src = op.bh + (size_t)(n0 + row) * K + kc + seg * 8;
            else             src = op.bl + (size_t)(n0 + row) * K + kc + seg * 8;
            cp16(sa, src);
        }
        asm volatile("cp.async.commit_group;" ::: "memory");
    };

    prefetch(0, 0);

    for (int c = 0; c < nch; ++c) {
        if (c + 1 < nch) {
            prefetch(c + 1, (c + 1) & 1);
            asm volatile("cp.async.wait_group 1;" ::: "memory");
        } else {
            asm volatile("cp.async.wait_group 0;" ::: "memory");
        }
        __syncthreads();

        const uint32_t sbase = sb + (uint32_t)(c & 1) * STAGE_B_;
        #pragma unroll
        for (int p = 0; p < 3; ++p) {
            const uint32_t Ab = sbase + (p == 2 ? TILE_B_ : 0);
            const uint32_t Bb = sbase + (p == 1 ? 3 * TILE_B_ : 2 * TILE_B_);
            #pragma unroll
            for (int ks = 0; ks < 4; ++ks) {
                const uint32_t aCol = ((uint32_t)(ks * 32) + aSel) ^ swz;
                const uint32_t bCol = ((uint32_t)(ks * 32) + bSel) ^ swz;
                uint32_t a[4][4];
                #pragma unroll
                for (int mb = 0; mb < 4; ++mb)
                    ldsm4(a[mb][0], a[mb][1], a[mb][2], a[mb][3],
                          Ab + (uint32_t)(aRow0 + mb * 16) * 128 + aCol);
                #pragma unroll
                for (int nb = 0; nb < 2; ++nb) {
                    uint32_t b0, b1, b2, b3;
                    ldsm4(b0, b1, b2, b3,
                          Bb + (uint32_t)(bRow0 + nb * 16) * 128 + bCol);
                    #pragma unroll
                    for (int mb = 0; mb < 4; ++mb) {
                        mma16816(acc[mb][nb * 2 + 0], a[mb], b0, b1);
                        mma16816(acc[mb][nb * 2 + 1], a[mb], b2, b3);
                    }
                }
            }
        }
        __syncthreads();
    }

    // ---- epilogue: bias (+GELU), fp32 and/or bf16-split stores ----
    const int rbase = m0 + wm * 64 + (l >> 2);
    const int cbase = n0 + wn * 32 + (l & 3) * 2;
    #pragma unroll
    for (int mb = 0; mb < 4; ++mb) {
        #pragma unroll
        for (int nblk = 0; nblk < 4; ++nblk) {
            const int col = cbase + nblk * 8;
            const float bx = op.bias[col], by = op.bias[col + 1];
            float v[4] = { acc[mb][nblk][0] + bx, acc[mb][nblk][1] + by,
                           acc[mb][nblk][2] + bx, acc[mb][nblk][3] + by };
            if (GELU) {
                #pragma unroll
                for (int e = 0; e < 4; ++e)
                    v[e] = 0.5f * v[e] * (1.0f + erff(v[e] * 0.70710678118654752440f));
            }
            const int row = rbase + mb * 16;
            if (op.c) {
                float2 lo; lo.x = v[0]; lo.y = v[1];
                float2 hi; hi.x = v[2]; hi.y = v[3];
                *(float2*)(op.c + (size_t)row * N + col)       = lo;
                *(float2*)(op.c + (size_t)(row + 8) * N + col) = hi;
            }
            if (op.oh) {
                __nv_bfloat162 h0, l0, h1, l1;
                h0.x = __float2bfloat16(v[0]);
                h0.y = __float2bfloat16(v[1]);
                l0.x = __float2bfloat16(v[0] - __bfloat162float(h0.x));
                l0.y = __float2bfloat16(v[1] - __bfloat162float(h0.y));
                h1.x = __float2bfloat16(v[2]);
                h1.y = __float2bfloat16(v[3]);
                l1.x = __float2bfloat16(v[2] - __bfloat162float(h1.x));
                l1.y = __float2bfloat16(v[3] - __bfloat162float(h1.y));
                *(__nv_bfloat162*)(op.oh + (size_t)row * N + col)       = h0;
                *(__nv_bfloat162*)(op.ol + (size_t)row * N + col)       = l0;
                *(__nv_bfloat162*)(op.oh + (size_t)(row + 8) * N + col) = h1;
                *(__nv_bfloat162*)(op.ol + (size_t)(row + 8) * N + col) = l1;
            }
        }
    }
}

// -------------------- weight transpose + split: W[K,N] -> Wt[N,K] -----------
__global__ void wtrans_kernel(const float* __restrict__ W,
                              __nv_bfloat16* __restrict__ th,
                              __nv_bfloat16* __restrict__ tl, int Kd, int Nd)
{
    __shared__ float t[32][33];
    const size_t lo_ = (size_t)blockIdx.z * Kd * Nd;
    const float* Wp = W + lo_;
    __nv_bfloat16* thp = th + lo_;
    __nv_bfloat16* tlp = tl + lo_;
    const int n0 = blockIdx.x * 32, k0 = blockIdx.y * 32;
    const int tx = threadIdx.x & 31, ty = threadIdx.x >> 5;

    #pragma unroll
    for (int j = 0; j < 32; j += 8)
        t[ty + j][tx] = Wp[(size_t)(k0 + ty + j) * Nd + n0 + tx];
    __syncthreads();
    #pragma unroll
    for (int j = 0; j < 32; j += 8) {
        const float v = t[tx][ty + j];
        const __nv_bfloat16 h = __float2bfloat16(v);
        const size_t o = (size_t)(n0 + ty + j) * Kd + k0 + tx;
        thp[o] = h;
        tlp[o] = __float2bfloat16(v - __bfloat162float(h));
    }
}

// fused transpose+split for the four DxD weight families (one launch)
struct W4 { const float* w; __nv_bfloat16* th; __nv_bfloat16* tl; };
__global__ void wtrans4_kernel(W4 a, W4 b, W4 c, W4 d)
{
    __shared__ float t[32][33];
    const int which = blockIdx.z & 3;
    const int lyr   = blockIdx.z >> 2;
    const W4 s = (which == 0) ? a : (which == 1) ? b : (which == 2) ? c : d;
    const size_t lo_ = (size_t)lyr * D_ * D_;
    const float* Wp = s.w + lo_;
    __nv_bfloat16* thp = s.th + lo_;
    __nv_bfloat16* tlp = s.tl + lo_;
    const int n0 = blockIdx.x * 32, k0 = blockIdx.y * 32;
    const int tx = threadIdx.x & 31, ty = threadIdx.x >> 5;

    #pragma unroll
    for (int j = 0; j < 32; j += 8)
        t[ty + j][tx] = Wp[(size_t)(k0 + ty + j) * D_ + n0 + tx];
    __syncthreads();
    #pragma unroll
    for (int j = 0; j < 32; j += 8) {
        const float v = t[tx][ty + j];
        const __nv_bfloat16 h = __float2bfloat16(v);
        const size_t o = (size_t)(n0 + ty + j) * D_ + k0 + tx;
        thp[o] = h;
        tlp[o] = __float2bfloat16(v - __bfloat162float(h));
    }
}

// -------------------- positional-encoding table -----------------------------
__global__ void pe_kernel(float* __restrict__ pe)
{
    const int s = blockIdx.x;
    for (int c = threadIdx.x; c < D_; c += blockDim.x) {
        const int j = c >> 1;
        const double e   = (double)(4 * j) / 768.0;
        const double inv = pow(10000.0, -e);
        const float  arg = (float)((double)s * inv);
        pe[s * D_ + c] = (c & 1) ? cosf(arg) : sinf(arg);
    }
}

// -------------------- embedding (fp32 + splits) -----------------------------
__global__ void embed_kernel(const int* __restrict__ x, const int* __restrict__ seg,
                             const float* __restrict__ tok, const float* __restrict__ se,
                             const float* __restrict__ pe, float* __restrict__ h,
                             __nv_bfloat16* __restrict__ sh, __nv_bfloat16* __restrict__ sl)
{
    const int t   = blockIdx.x;
    const int tid = threadIdx.x;
    const int s   = t & (S_ - 1);
    const int xi  = x[t];
    const int si  = seg[t];
    const size_t base = (size_t)t * D_;
    #pragma unroll
    for (int u = 0; u < 3; ++u) {
        const int c = tid + u * 256;
        const float v = tok[(size_t)xi * D_ + c] + se[(size_t)si * D_ + c] + pe[s * D_ + c];
        h[base + c] = v;
        const __nv_bfloat16 hb = __float2bfloat16(v);
        sh[base + c] = hb;
        sl[base + c] = __float2bfloat16(v - __bfloat162float(hb));
    }
}

// -------------------- fused attention: scores+softmax+PV (emit splits) ------
// grid = B*H (1536), block = 256. Smem reuse: Qs->P, Ks->V after score phase.
__global__ void attn_fused_kernel(const float* __restrict__ q, const float* __restrict__ k,
                                  const float* __restrict__ v, const int* __restrict__ x,
                                  __nv_bfloat16* __restrict__ oh, __nv_bfloat16* __restrict__ ol)
{
    __shared__ float Qs[S_ * 65];     // phase 1: Q      phase 2: P
    __shared__ float Ks[S_ * 65];     // phase 1: K      phase 2: V (flat 64-stride)
    __shared__ int   mk[S_];

    const int bh = blockIdx.x;
    const int b  = bh / H_;
    const int h  = bh % H_;
    const int tid = threadIdx.x;

    const float* qbase = q + (size_t)(b * S_) * D_ + h * DK_;
    const float* kbase = k + (size_t)(b * S_) * D_ + h * DK_;
    const float* vbase = v + (size_t)(b * S_) * D_ + h * DK_;

    for (int idx = tid; idx < S_ * DK_; idx += 256) {
        const int r = idx >> 6, d = idx & 63;
        Qs[r * 65 + d] = qbase[(size_t)r * D_ + d];
        Ks[r * 65 + d] = kbase[(size_t)r * D_ + d];
    }
    if (tid < S_) mk[tid] = x[b * S_ + tid];
    __syncthreads();

    const int row = tid >> 2;          // query row 0..63
    const int jc  = (tid & 3) * 16;    // key-col block

    float sc[16];
    #pragma unroll
    for (int jj = 0; jj < 16; ++jj) sc[jj] = 0.0f;

    for (int d = 0; d < DK_; ++d) {
        const float qv = Qs[row * 65 + d];
        #pragma unroll
        for (int jj = 0; jj < 16; ++jj)
            sc[jj] += qv * Ks[(jc + jj) * 65 + d];
    }

    float mx = -3.0e38f;
    #pragma unroll
    for (int jj = 0; jj < 16; ++jj) {
        const float val = (mk[jc + jj] > 0) ? sc[jj] * 0.125f : -1.0e9f;
        sc[jj] = val;
        mx = fmaxf(mx, val);
    }
    mx = fmaxf(mx, __shfl_xor_sync(0xffffffffu, mx, 1));
    mx = fmaxf(mx, __shfl_xor_sync(0xffffffffu, mx, 2));

    float sum = 0.0f;
    #pragma unroll
    for (int jj = 0; jj < 16; ++jj) {
        sc[jj] = expf(sc[jj] - mx);
        sum += sc[jj];
    }
    sum += __shfl_xor_sync(0xffffffffu, sum, 1);
    sum += __shfl_xor_sync(0xffffffffu, sum, 2);
    const float pinv = 1.0f / sum;

    __syncthreads();   // all Qs/Ks reads of phase 1/2 complete

    // write P into Qs, load V into Ks (flat, stride 64)
    #pragma unroll
    for (int jj = 0; jj < 16; ++jj) Qs[row * 65 + jc + jj] = sc[jj] * pinv;
    for (int idx = tid; idx < S_ * DK_; idx += 256)
        Ks[idx] = vbase[(size_t)(idx >> 6) * D_ + (idx & 63)];
    __syncthreads();

    // ctx = P @ V : thread owns (row, 16 headdims at d0)
    const int d0 = (tid & 3) * 16;
    float acc[16];
    #pragma unroll
    for (int dd = 0; dd < 16; ++dd) acc[dd] = 0.0f;

    for (int j = 0; j < S_; ++j) {
        const float p = Qs[row * 65 + j];
        #pragma unroll
        for (int dd = 0; dd < 16; ++dd)
            acc[dd] += p * Ks[j * DK_ + d0 + dd];
    }

    const size_t obase = (size_t)(b * S_ + row) * D_ + h * DK_ + d0;
    #pragma unroll
    for (int dd = 0; dd < 16; dd += 2) {
        __nv_bfloat162 hb, lb;
        hb.x = __float2bfloat16(acc[dd]);
        hb.y = __float2bfloat16(acc[dd + 1]);
        lb.x = __float2bfloat16(acc[dd]     - __bfloat162float(hb.x));
        lb.y = __float2bfloat16(acc[dd + 1] - __bfloat162float(hb.y));
        *(__nv_bfloat162*)(oh + obase + dd) = hb;
        *(__nv_bfloat162*)(ol + obase + dd) = lb;
    }
}

// -------------------- residual add + layernorm (fp32 + splits) --------------
__global__ void resid_ln_kernel(const float* __restrict__ a, const float* __restrict__ r,
                                const float* __restrict__ g, const float* __restrict__ be,
                                float* __restrict__ out,
                                __nv_bfloat16* __restrict__ oh, __nv_bfloat16* __restrict__ ol)
{
    const int t   = blockIdx.x;
    const int tid = threadIdx.x;
    const size_t base = (size_t)t * D_;

    const float y0 = a[base + tid]       + r[base + tid];
    const float y1 = a[base + tid + 256] + r[base + tid + 256];
    const float y2 = a[base + tid + 512] + r[base + tid + 512];

    __shared__ float red[256];
    red[tid] = y0 + y1 + y2;
    __syncthreads();
    #pragma unroll
    for (int o = 128; o > 0; o >>= 1) {
        if (tid < o) red[tid] += red[tid + o];
        __syncthreads();
    }
    const float mu = red[0] * (1.0f / 768.0f);
    __syncthreads();

    const float d0 = y0 - mu, d1 = y1 - mu, d2 = y2 - mu;
    red[tid] = d0 * d0 + d1 * d1 + d2 * d2;
    __syncthreads();
    #pragma unroll
    for (int o = 128; o > 0; o >>= 1) {
        if (tid < o) red[tid] += red[tid + o];
        __syncthreads();
    }
    const float var = red[0] * (1.0f / 768.0f);
    const float inv = rsqrtf(var + 1e-5f);

    const float o0 = d0 * inv * g[tid]       + be[tid];
    const float o1 = d1 * inv * g[tid + 256] + be[tid + 256];
    const float o2 = d2 * inv * g[tid + 512] + be[tid + 512];
    out[base + tid]       = o0;
    out[base + tid + 256] = o1;
    out[base + tid + 512] = o2;

    const __nv_bfloat16 h0 = __float2bfloat16(o0);
    const __nv_bfloat16 h1 = __float2bfloat16(o1);
    const __nv_bfloat16 h2 = __float2bfloat16(o2);
    oh[base + tid]       = h0;
    oh[base + tid + 256] = h1;
    oh[base + tid + 512] = h2;
    ol[base + tid]       = __float2bfloat16(o0 - __bfloat162float(h0));
    ol[base + tid + 256] = __float2bfloat16(o1 - __bfloat162float(h1));
    ol[base + tid + 512] = __float2bfloat16(o2 - __bfloat162float(h2));
}

// ---------------------------------------------------------------------------
extern "C" void kernel_launch(void* const* d_in, const int* in_sizes, int n_in,
                              void* d_out, int out_size)
{
    const int*   x    = (const int*)  d_in[0];
    const int*   seg  = (const int*)  d_in[1];
    const float* tok  = (const float*)d_in[2];
    const float* se   = (const float*)d_in[3];
    const float* Wq   = (const float*)d_in[4];
    const float* bq   = (const float*)d_in[5];
    const float* Wk   = (const float*)d_in[6];
    const float* bk   = (const float*)d_in[7];
    const float* Wv   = (const float*)d_in[8];
    const float* bv   = (const float*)d_in[9];
    const float* Wo   = (const float*)d_in[10];
    const float* bo   = (const float*)d_in[11];
    const float* lng  = (const float*)d_in[12];
    const float* lnb  = (const float*)d_in[13];
    const float* W1   = (const float*)d_in[14];
    const float* b1   = (const float*)d_in[15];
    const float* W2   = (const float*)d_in[16];
    const float* b2   = (const float*)d_in[17];
    float* out = (float*)d_out;

    float *h, *h1, *q, *k, *v, *tmp, *pe;
    __nv_bfloat16 *ah, *al, *sh, *sl;
    __nv_bfloat16 *wqh, *wql, *wkh, *wkl, *wvh, *wvl, *woh, *wol, *w1h, *w1l, *w2h, *w2l;
    cudaGetSymbolAddress((void**)&h,     g_h);
    cudaGetSymbolAddress((void**)&h1,    g_h1);
    cudaGetSymbolAddress((void**)&q,     g_q);
    cudaGetSymbolAddress((void**)&k,     g_k);
    cudaGetSymbolAddress((void**)&v,     g_v);
    cudaGetSymbolAddress((void**)&tmp,   g_tmp);
    cudaGetSymbolAddress((void**)&pe,    g_pe);
    cudaGetSymbolAddress((void**)&ah,    g_ah);
    cudaGetSymbolAddress((void**)&al,    g_al);
    cudaGetSymbolAddress((void**)&sh,    g_sh);
    cudaGetSymbolAddress((void**)&sl,    g_sl);
    cudaGetSymbolAddress((void**)&wqh,   g_wqh);
    cudaGetSymbolAddress((void**)&wql,   g_wql);
    cudaGetSymbolAddress((void**)&wkh,   g_wkh);
    cudaGetSymbolAddress((void**)&wkl,   g_wkl);
    cudaGetSymbolAddress((void**)&wvh,   g_wvh);
    cudaGetSymbolAddress((void**)&wvl,   g_wvl);
    cudaGetSymbolAddress((void**)&woh,   g_woh);
    cudaGetSymbolAddress((void**)&wol,   g_wol);
    cudaGetSymbolAddress((void**)&w1h,   g_w1h);
    cudaGetSymbolAddress((void**)&w1l,   g_w1l);
    cudaGetSymbolAddress((void**)&w2h,   g_w2h);
    cudaGetSymbolAddress((void**)&w2l,   g_w2l);

    cudaFuncSetAttribute(gemm_kernel<false>, cudaFuncAttributeMaxDynamicSharedMemorySize, GSMEM_);
    cudaFuncSetAttribute(gemm_kernel<true >, cudaFuncAttributeMaxDynamicSharedMemorySize, GSMEM_);

    // ---- setup ----
    {
        W4 aq = { Wq, wqh, wql }, ak = { Wk, wkh, wkl };
        W4 av = { Wv, wvh, wvl }, ao = { Wo, woh, wol };
        wtrans4_kernel<<<dim3(24, 24, 4 * L_), 256>>>(aq, ak, av, ao);
    }
    wtrans_kernel<<<dim3(96, 24, L_), 256>>>(W1, w1h, w1l, D_, FF_);
    wtrans_kernel<<<dim3(24, 96, L_), 256>>>(W2, w2h, w2l, FF_, D_);
    pe_kernel<<<S_, 256>>>(pe);
    embed_kernel<<<NT_, 256>>>(x, seg, tok, se, pe, h, sh, sl);

    const dim3 gP(D_ / BN_, NT_ / BM_, 1);    // (6, 64)  N=768 GEMMs
    const dim3 gQKV(D_ / BN_, NT_ / BM_, 3);  // fused QKV
    const dim3 gF(FF_ / BN_, NT_ / BM_, 1);   // (24, 64) FF1

    for (int l = 0; l < L_; ++l) {
        const size_t wOff  = (size_t)l * D_ * D_;
        const size_t fOff1 = (size_t)l * D_ * FF_;
        const size_t fOff2 = (size_t)l * FF_ * D_;

        {   // QKV from h-splits
            BOp oq = { wqh + wOff, wql + wOff, bq + l * D_, q,   nullptr, nullptr };
            BOp ok = { wkh + wOff, wkl + wOff, bk + l * D_, k,   nullptr, nullptr };
            BOp ov = { wvh + wOff, wvl + wOff, bv + l * D_, v,   nullptr, nullptr };
            gemm_kernel<false><<<gQKV, GT_, GSMEM_>>>(sh, sl, oq, ok, ov, D_, D_);
        }

        attn_fused_kernel<<<B_ * H_, 256>>>(q, k, v, x, sh, sl);   // ctx splits

        {   // O projection from ctx-splits
            BOp oo = { woh + wOff, wol + wOff, bo + l * D_, tmp, nullptr, nullptr };
            gemm_kernel<false><<<gP, GT_, GSMEM_>>>(sh, sl, oo, oo, oo, D_, D_);
        }
        resid_ln_kernel<<<NT_, 256>>>(tmp, h, lng + l * D_, lnb + l * D_, h1, sh, sl);

        {   // FF1 (+GELU) from h1-splits -> ff splits (pairA), no fp32 output
            BOp o1 = { w1h + fOff1, w1l + fOff1, b1 + l * FF_, nullptr, ah, al };
            gemm_kernel<true><<<gF, GT_, GSMEM_>>>(sh, sl, o1, o1, o1, D_, FF_);
        }
        {   // FF2 from ff-splits
            BOp o2 = { w2h + fOff2, w2l + fOff2, b2 + l * D_, tmp, nullptr, nullptr };
            gemm_kernel<false><<<gP, GT_, GSMEM_>>>(ah, al, o2, o2, o2, FF_, D_);
        }

        float* dst = (l == L_ - 1) ? out : h;
        resid_ln_kernel<<<NT_, 256>>>(tmp, h1, lng + l * D_, lnb + l * D_, dst, sh, sl);
    }
}

// round 12
// speedup vs baseline: 1.8579x; 1.5684x over previous
#include <cuda_runtime.h>
#include <cuda_fp16.h>
#include <math.h>
#include <stdint.h>

// ---------------------------------------------------------------------------
// BERT-base forward (B=128, S=64, D=768, H=12, L=12, FF=3072).
// GEMMs: mma.sync (HMMA) fp16 2-pass: C = Ah*(Bh + Bl), fp32 accumulators.
//   - weights pre-split hi/lo fp16 (22 effective mantissa bits)
//   - activations single fp16 (residual term dropped; ~2^-12 rel error)
// 256 thr, 128x128x64 tiles, 2-stage cp.async, 2 CTAs/SM (48 KB/stage).
// Attention / LayerNorm / embedding: fp32 CUDA-core kernels.
// ---------------------------------------------------------------------------

#define B_    128
#define S_    64
#define D_    768
#define H_    12
#define DK_   64
#define FF_   3072
#define L_    12
#define NT_   (B_ * S_)          // 8192 tokens

// -------------------- scratch (device globals; no allocs) -------------------
__device__ float g_h   [NT_ * D_];
__device__ float g_h1  [NT_ * D_];
__device__ float g_q   [NT_ * D_];
__device__ float g_k   [NT_ * D_];
__device__ float g_v   [NT_ * D_];
__device__ float g_tmp [NT_ * D_];
__device__ float g_pe  [S_ * D_];

// fp16 activations: pairA (FF-sized, FF1 out), pairB (D-sized, h/ctx/h1)
__device__ __half g_ah[NT_ * FF_];
__device__ __half g_sh[NT_ * D_];

// fp16 split transposed weights: [L][N][K] layout (K contiguous per row)
__device__ __half g_wqh[L_ * D_ * D_];
__device__ __half g_wql[L_ * D_ * D_];
__device__ __half g_wkh[L_ * D_ * D_];
__device__ __half g_wkl[L_ * D_ * D_];
__device__ __half g_wvh[L_ * D_ * D_];
__device__ __half g_wvl[L_ * D_ * D_];
__device__ __half g_woh[L_ * D_ * D_];
__device__ __half g_wol[L_ * D_ * D_];
__device__ __half g_w1h[L_ * FF_ * D_];   // [L][3072][768]
__device__ __half g_w1l[L_ * FF_ * D_];
__device__ __half g_w2h[L_ * D_ * FF_];   // [L][768][3072]
__device__ __half g_w2l[L_ * D_ * FF_];

// -------------------- PTX helpers (all arch-agnostic, sm_80+) ---------------
__device__ __forceinline__ uint32_t smem_u32(const void* p) {
    uint32_t a;
    asm("{ .reg .u64 t; cvta.to.shared.u64 t, %1; cvt.u32.u64 %0, t; }"
        : "=r"(a) : "l"(p));
    return a;
}
__device__ __forceinline__ void cp16(uint32_t s, const void* g) {
    asm volatile("cp.async.cg.shared.global [%0], [%1], 16;" :: "r"(s), "l"(g) : "memory");
}
__device__ __forceinline__ void ldsm4(uint32_t& r0, uint32_t& r1, uint32_t& r2,
                                      uint32_t& r3, uint32_t a) {
    asm volatile("ldmatrix.sync.aligned.m8n8.x4.shared.b16 {%0,%1,%2,%3}, [%4];"
                 : "=r"(r0), "=r"(r1), "=r"(r2), "=r"(r3) : "r"(a));
}
__device__ __forceinline__ void mma16816(float* c, const uint32_t* a,
                                         uint32_t b0, uint32_t b1) {
    asm volatile("mma.sync.aligned.m16n8k16.row.col.f32.f16.f16.f32 "
                 "{%0,%1,%2,%3}, {%4,%5,%6,%7}, {%8,%9}, {%0,%1,%2,%3};"
                 : "+f"(c[0]), "+f"(c[1]), "+f"(c[2]), "+f"(c[3])
                 : "r"(a[0]), "r"(a[1]), "r"(a[2]), "r"(a[3]), "r"(b0), "r"(b1));
}

// -------------------- HMMA fp16 2-pass GEMM ---------------------------------
// C[8192, N] = A[8192, K] @ W[K, N] + bias (+GELU). A single fp16; W split
// hi/lo fp16, pre-transposed to Bt[N, K]. CTA tile 128x128, BK=64.
// Output: fp32 (op.c) and/or fp16 (op.oh).
struct BOp { const __half* bh; const __half* bl;
             const float* bias; float* c; __half* oh; };

#define GT_       256
#define BM_       128
#define BN_       128
#define BK_       64
#define TILE_B_   16384u       // 128 rows x 128 bytes
#define STAGE_B_  49152u       // A, Bh, Bl
#define GSMEM_    (2 * 49152)

template <bool GELU>
__global__ __launch_bounds__(GT_, 2)
void gemm_kernel(const __half* __restrict__ A,
                 BOp op0, BOp op1, BOp op2, int K, int N)
{
    extern __shared__ char smem[];
    const uint32_t sb = smem_u32(smem);
    const int tid = threadIdx.x, wid = tid >> 5, l = tid & 31;
    const int wm = wid & 1;          // 2 warps along M
    const int wn = wid >> 1;         // 4 warps along N
    const BOp op = (blockIdx.z == 0) ? op0 : ((blockIdx.z == 1) ? op1 : op2);
    const int m0 = blockIdx.y * BM_;
    const int n0 = blockIdx.x * BN_;

    // per-lane ldmatrix addressing components
    const uint32_t swz  = (uint32_t)((l & 7) << 4);
    const int aRow0     = wm * 64 + ((l >> 3) & 1) * 8 + (l & 7);
    const uint32_t aSel = (uint32_t)(((l >> 4) & 1) * 16);
    const int bRow0     = wn * 32 + ((l >> 4) & 1) * 8 + (l & 7);
    const uint32_t bSel = (uint32_t)(((l >> 3) & 1) * 16);

    float acc[4][4][4];
    #pragma unroll
    for (int i = 0; i < 4; ++i)
        #pragma unroll
        for (int j = 0; j < 4; ++j)
            #pragma unroll
            for (int e = 0; e < 4; ++e) acc[i][j][e] = 0.0f;

    const int nch = K / BK_;

    // ---- async prefetch of one stage (A|Bh|Bl tiles): 12 cp16/thread ----
    auto prefetch = [&](int c, int s) {
        const int kc = c * BK_;
        const uint32_t sbase = sb + (uint32_t)s * STAGE_B_;
        #pragma unroll 4
        for (int g = tid; g < 3072; g += GT_) {
            const int t   = g >> 10;                 // 0=A, 1=Bh, 2=Bl
            const int idx = g & 1023;
            const int row = idx >> 3, seg = idx & 7;
            const uint32_t sa = sbase + (uint32_t)t * TILE_B_ + (uint32_t)row * 128
                              + (((uint32_t)(seg * 16)) ^ ((uint32_t)(row & 7) << 4));
            const __half* src;
            if      (t == 0) src = A     + (size_t)(m0 + row) * K + kc + seg * 8;
            else if (t == 1) src = op.bh + (size_t)(n0 + row) * K + kc + seg * 8;
            else             src = op.bl + (size_t)(n0 + row) * K + kc + seg * 8;
            cp16(sa, src);
        }
        asm volatile("cp.async.commit_group;" ::: "memory");
    };

    prefetch(0, 0);

    for (int c = 0; c < nch; ++c) {
        if (c + 1 < nch) {
            prefetch(c + 1, (c + 1) & 1);
            asm volatile("cp.async.wait_group 1;" ::: "memory");
        } else {
            asm volatile("cp.async.wait_group 0;" ::: "memory");
        }
        __syncthreads();

        const uint32_t sbase = sb + (uint32_t)(c & 1) * STAGE_B_;
        #pragma unroll
        for (int ks = 0; ks < 4; ++ks) {
            const uint32_t aCol = ((uint32_t)(ks * 32) + aSel) ^ swz;
            const uint32_t bCol = ((uint32_t)(ks * 32) + bSel) ^ swz;
            uint32_t a[4][4];
            #pragma unroll
            for (int mb = 0; mb < 4; ++mb)
                ldsm4(a[mb][0], a[mb][1], a[mb][2], a[mb][3],
                      sbase + (uint32_t)(aRow0 + mb * 16) * 128 + aCol);
            #pragma unroll
            for (int p = 0; p < 2; ++p) {           // Bh then Bl, reuse A regs
                const uint32_t Bb = sbase + TILE_B_ + (uint32_t)p * TILE_B_;
                #pragma unroll
                for (int nb = 0; nb < 2; ++nb) {
                    uint32_t b0, b1, b2, b3;
                    ldsm4(b0, b1, b2, b3,
                          Bb + (uint32_t)(bRow0 + nb * 16) * 128 + bCol);
                    #pragma unroll
                    for (int mb = 0; mb < 4; ++mb) {
                        mma16816(acc[mb][nb * 2 + 0], a[mb], b0, b1);
                        mma16816(acc[mb][nb * 2 + 1], a[mb], b2, b3);
                    }
                }
            }
        }
        __syncthreads();
    }

    // ---- epilogue: bias (+GELU), fp32 and/or fp16 stores ----
    const int rbase = m0 + wm * 64 + (l >> 2);
    const int cbase = n0 + wn * 32 + (l & 3) * 2;
    #pragma unroll
    for (int mb = 0; mb < 4; ++mb) {
        #pragma unroll
        for (int nblk = 0; nblk < 4; ++nblk) {
            const int col = cbase + nblk * 8;
            const float bx = op.bias[col], by = op.bias[col + 1];
            float v[4] = { acc[mb][nblk][0] + bx, acc[mb][nblk][1] + by,
                           acc[mb][nblk][2] + bx, acc[mb][nblk][3] + by };
            if (GELU) {
                #pragma unroll
                for (int e = 0; e < 4; ++e)
                    v[e] = 0.5f * v[e] * (1.0f + erff(v[e] * 0.70710678118654752440f));
            }
            const int row = rbase + mb * 16;
            if (op.c) {
                float2 lo; lo.x = v[0]; lo.y = v[1];
                float2 hi; hi.x = v[2]; hi.y = v[3];
                *(float2*)(op.c + (size_t)row * N + col)       = lo;
                *(float2*)(op.c + (size_t)(row + 8) * N + col) = hi;
            }
            if (op.oh) {
                __half2 h0, h1;
                h0.x = __float2half_rn(v[0]);
                h0.y = __float2half_rn(v[1]);
                h1.x = __float2half_rn(v[2]);
                h1.y = __float2half_rn(v[3]);
                *(__half2*)(op.oh + (size_t)row * N + col)       = h0;
                *(__half2*)(op.oh + (size_t)(row + 8) * N + col) = h1;
            }
        }
    }
}

// -------------------- weight transpose + fp16 hi/lo split -------------------
__global__ void wtrans_kernel(const float* __restrict__ W,
                              __half* __restrict__ th,
                              __half* __restrict__ tl, int Kd, int Nd)
{
    __shared__ float t[32][33];
    const size_t lo_ = (size_t)blockIdx.z * Kd * Nd;
    const float* Wp = W + lo_;
    __half* thp = th + lo_;
    __half* tlp = tl + lo_;
    const int n0 = blockIdx.x * 32, k0 = blockIdx.y * 32;
    const int tx = threadIdx.x & 31, ty = threadIdx.x >> 5;

    #pragma unroll
    for (int j = 0; j < 32; j += 8)
        t[ty + j][tx] = Wp[(size_t)(k0 + ty + j) * Nd + n0 + tx];
    __syncthreads();
    #pragma unroll
    for (int j = 0; j < 32; j += 8) {
        const float v = t[tx][ty + j];
        const __half h = __float2half_rn(v);
        const size_t o = (size_t)(n0 + ty + j) * Kd + k0 + tx;
        thp[o] = h;
        tlp[o] = __float2half_rn(v - __half2float(h));
    }
}

// fused transpose+split for the four DxD weight families (one launch)
struct W4 { const float* w; __half* th; __half* tl; };
__global__ void wtrans4_kernel(W4 a, W4 b, W4 c, W4 d)
{
    __shared__ float t[32][33];
    const int which = blockIdx.z & 3;
    const int lyr   = blockIdx.z >> 2;
    const W4 s = (which == 0) ? a : (which == 1) ? b : (which == 2) ? c : d;
    const size_t lo_ = (size_t)lyr * D_ * D_;
    const float* Wp = s.w + lo_;
    __half* thp = s.th + lo_;
    __half* tlp = s.tl + lo_;
    const int n0 = blockIdx.x * 32, k0 = blockIdx.y * 32;
    const int tx = threadIdx.x & 31, ty = threadIdx.x >> 5;

    #pragma unroll
    for (int j = 0; j < 32; j += 8)
        t[ty + j][tx] = Wp[(size_t)(k0 + ty + j) * D_ + n0 + tx];
    __syncthreads();
    #pragma unroll
    for (int j = 0; j < 32; j += 8) {
        const float v = t[tx][ty + j];
        const __half h = __float2half_rn(v);
        const size_t o = (size_t)(n0 + ty + j) * D_ + k0 + tx;
        thp[o] = h;
        tlp[o] = __float2half_rn(v - __half2float(h));
    }
}

// -------------------- positional-encoding table -----------------------------
__global__ void pe_kernel(float* __restrict__ pe)
{
    const int s = blockIdx.x;
    for (int c = threadIdx.x; c < D_; c += blockDim.x) {
        const int j = c >> 1;
        const double e   = (double)(4 * j) / 768.0;
        const double inv = pow(10000.0, -e);
        const float  arg = (float)((double)s * inv);
        pe[s * D_ + c] = (c & 1) ? cosf(arg) : sinf(arg);
    }
}

// -------------------- embedding (fp32 + fp16) -------------------------------
__global__ void embed_kernel(const int* __restrict__ x, const int* __restrict__ seg,
                             const float* __restrict__ tok, const float* __restrict__ se,
                             const float* __restrict__ pe, float* __restrict__ h,
                             __half* __restrict__ sh)
{
    const int t   = blockIdx.x;
    const int tid = threadIdx.x;
    const int s   = t & (S_ - 1);
    const int xi  = x[t];
    const int si  = seg[t];
    const size_t base = (size_t)t * D_;
    #pragma unroll
    for (int u = 0; u < 3; ++u) {
        const int c = tid + u * 256;
        const float v = tok[(size_t)xi * D_ + c] + se[(size_t)si * D_ + c] + pe[s * D_ + c];
        h[base + c] = v;
        sh[base + c] = __float2half_rn(v);
    }
}

// -------------------- fused attention: scores+softmax+PV (emit fp16) --------
// grid = B*H (1536), block = 256. Smem reuse: Qs->P, Ks->V after score phase.
__global__ void attn_fused_kernel(const float* __restrict__ q, const float* __restrict__ k,
                                  const float* __restrict__ v, const int* __restrict__ x,
                                  __half* __restrict__ oh)
{
    __shared__ float Qs[S_ * 65];     // phase 1: Q      phase 2: P
    __shared__ float Ks[S_ * 65];     // phase 1: K      phase 2: V (flat 64-stride)
    __shared__ int   mk[S_];

    const int bh = blockIdx.x;
    const int b  = bh / H_;
    const int h  = bh % H_;
    const int tid = threadIdx.x;

    const float* qbase = q + (size_t)(b * S_) * D_ + h * DK_;
    const float* kbase = k + (size_t)(b * S_) * D_ + h * DK_;
    const float* vbase = v + (size_t)(b * S_) * D_ + h * DK_;

    for (int idx = tid; idx < S_ * DK_; idx += 256) {
        const int r = idx >> 6, d = idx & 63;
        Qs[r * 65 + d] = qbase[(size_t)r * D_ + d];
        Ks[r * 65 + d] = kbase[(size_t)r * D_ + d];
    }
    if (tid < S_) mk[tid] = x[b * S_ + tid];
    __syncthreads();

    const int row = tid >> 2;          // query row 0..63
    const int jc  = (tid & 3) * 16;    // key-col block

    float sc[16];
    #pragma unroll
    for (int jj = 0; jj < 16; ++jj) sc[jj] = 0.0f;

    for (int d = 0; d < DK_; ++d) {
        const float qv = Qs[row * 65 + d];
        #pragma unroll
        for (int jj = 0; jj < 16; ++jj)
            sc[jj] += qv * Ks[(jc + jj) * 65 + d];
    }

    float mx = -3.0e38f;
    #pragma unroll
    for (int jj = 0; jj < 16; ++jj) {
        const float val = (mk[jc + jj] > 0) ? sc[jj] * 0.125f : -1.0e9f;
        sc[jj] = val;
        mx = fmaxf(mx, val);
    }
    mx = fmaxf(mx, __shfl_xor_sync(0xffffffffu, mx, 1));
    mx = fmaxf(mx, __shfl_xor_sync(0xffffffffu, mx, 2));

    float sum = 0.0f;
    #pragma unroll
    for (int jj = 0; jj < 16; ++jj) {
        sc[jj] = expf(sc[jj] - mx);
        sum += sc[jj];
    }
    sum += __shfl_xor_sync(0xffffffffu, sum, 1);
    sum += __shfl_xor_sync(0xffffffffu, sum, 2);
    const float pinv = 1.0f / sum;

    __syncthreads();   // all Qs/Ks reads of phase 1 complete

    // write P into Qs, load V into Ks (flat, stride 64)
    #pragma unroll
    for (int jj = 0; jj < 16; ++jj) Qs[row * 65 + jc + jj] = sc[jj] * pinv;
    for (int idx = tid; idx < S_ * DK_; idx += 256)
        Ks[idx] = vbase[(size_t)(idx >> 6) * D_ + (idx & 63)];
    __syncthreads();

    // ctx = P @ V : thread owns (row, 16 headdims at d0)
    const int d0 = (tid & 3) * 16;
    float acc[16];
    #pragma unroll
    for (int dd = 0; dd < 16; ++dd) acc[dd] = 0.0f;

    for (int j = 0; j < S_; ++j) {
        const float p = Qs[row * 65 + j];
        #pragma unroll
        for (int dd = 0; dd < 16; ++dd)
            acc[dd] += p * Ks[j * DK_ + d0 + dd];
    }

    const size_t obase = (size_t)(b * S_ + row) * D_ + h * DK_ + d0;
    #pragma unroll
    for (int dd = 0; dd < 16; dd += 2) {
        __half2 hb;
        hb.x = __float2half_rn(acc[dd]);
        hb.y = __float2half_rn(acc[dd + 1]);
        *(__half2*)(oh + obase + dd) = hb;
    }
}

// -------------------- residual add + layernorm (fp32 + fp16) ----------------
__global__ void resid_ln_kernel(const float* __restrict__ a, const float* __restrict__ r,
                                const float* __restrict__ g, const float* __restrict__ be,
                                float* __restrict__ out, __half* __restrict__ oh)
{
    const int t   = blockIdx.x;
    const int tid = threadIdx.x;
    const size_t base = (size_t)t * D_;

    const float y0 = a[base + tid]       + r[base + tid];
    const float y1 = a[base + tid + 256] + r[base + tid + 256];
    const float y2 = a[base + tid + 512] + r[base + tid + 512];

    __shared__ float red[256];
    red[tid] = y0 + y1 + y2;
    __syncthreads();
    #pragma unroll
    for (int o = 128; o > 0; o >>= 1) {
        if (tid < o) red[tid] += red[tid + o];
        __syncthreads();
    }
    const float mu = red[0] * (1.0f / 768.0f);
    __syncthreads();

    const float d0 = y0 - mu, d1 = y1 - mu, d2 = y2 - mu;
    red[tid] = d0 * d0 + d1 * d1 + d2 * d2;
    __syncthreads();
    #pragma unroll
    for (int o = 128; o > 0; o >>= 1) {
        if (tid < o) red[tid] += red[tid + o];
        __syncthreads();
    }
    const float var = red[0] * (1.0f / 768.0f);
    const float inv = rsqrtf(var + 1e-5f);

    const float o0 = d0 * inv * g[tid]       + be[tid];
    const float o1 = d1 * inv * g[tid + 256] + be[tid + 256];
    const float o2 = d2 * inv * g[tid + 512] + be[tid + 512];
    out[base + tid]       = o0;
    out[base + tid + 256] = o1;
    out[base + tid + 512] = o2;
    oh[base + tid]        = __float2half_rn(o0);
    oh[base + tid + 256]  = __float2half_rn(o1);
    oh[base + tid + 512]  = __float2half_rn(o2);
}

// ---------------------------------------------------------------------------
extern "C" void kernel_launch(void* const* d_in, const int* in_sizes, int n_in,
                              void* d_out, int out_size)
{
    const int*   x    = (const int*)  d_in[0];
    const int*   seg  = (const int*)  d_in[1];
    const float* tok  = (const float*)d_in[2];
    const float* se   = (const float*)d_in[3];
    const float* Wq   = (const float*)d_in[4];
    const float* bq   = (const float*)d_in[5];
    const float* Wk   = (const float*)d_in[6];
    const float* bk   = (const float*)d_in[7];
    const float* Wv   = (const float*)d_in[8];
    const float* bv   = (const float*)d_in[9];
    const float* Wo   = (const float*)d_in[10];
    const float* bo   = (const float*)d_in[11];
    const float* lng  = (const float*)d_in[12];
    const float* lnb  = (const float*)d_in[13];
    const float* W1   = (const float*)d_in[14];
    const float* b1   = (const float*)d_in[15];
    const float* W2   = (const float*)d_in[16];
    const float* b2   = (const float*)d_in[17];
    float* out = (float*)d_out;

    float *h, *h1, *q, *k, *v, *tmp, *pe;
    __half *ah, *sh;
    __half *wqh, *wql, *wkh, *wkl, *wvh, *wvl, *woh, *wol, *w1h, *w1l, *w2h, *w2l;
    cudaGetSymbolAddress((void**)&h,     g_h);
    cudaGetSymbolAddress((void**)&h1,    g_h1);
    cudaGetSymbolAddress((void**)&q,     g_q);
    cudaGetSymbolAddress((void**)&k,     g_k);
    cudaGetSymbolAddress((void**)&v,     g_v);
    cudaGetSymbolAddress((void**)&tmp,   g_tmp);
    cudaGetSymbolAddress((void**)&pe,    g_pe);
    cudaGetSymbolAddress((void**)&ah,    g_ah);
    cudaGetSymbolAddress((void**)&sh,    g_sh);
    cudaGetSymbolAddress((void**)&wqh,   g_wqh);
    cudaGetSymbolAddress((void**)&wql,   g_wql);
    cudaGetSymbolAddress((void**)&wkh,   g_wkh);
    cudaGetSymbolAddress((void**)&wkl,   g_wkl);
    cudaGetSymbolAddress((void**)&wvh,   g_wvh);
    cudaGetSymbolAddress((void**)&wvl,   g_wvl);
    cudaGetSymbolAddress((void**)&woh,   g_woh);
    cudaGetSymbolAddress((void**)&wol,   g_wol);
    cudaGetSymbolAddress((void**)&w1h,   g_w1h);
    cudaGetSymbolAddress((void**)&w1l,   g_w1l);
    cudaGetSymbolAddress((void**)&w2h,   g_w2h);
    cudaGetSymbolAddress((void**)&w2l,   g_w2l);

    cudaFuncSetAttribute(gemm_kernel<false>, cudaFuncAttributeMaxDynamicSharedMemorySize, GSMEM_);
    cudaFuncSetAttribute(gemm_kernel<true >, cudaFuncAttributeMaxDynamicSharedMemorySize, GSMEM_);

    // ---- setup ----
    {
        W4 aq = { Wq, wqh, wql }, ak = { Wk, wkh, wkl };
        W4 av = { Wv, wvh, wvl }, ao = { Wo, woh, wol };
        wtrans4_kernel<<<dim3(24, 24, 4 * L_), 256>>>(aq, ak, av, ao);
    }
    wtrans_kernel<<<dim3(96, 24, L_), 256>>>(W1, w1h, w1l, D_, FF_);
    wtrans_kernel<<<dim3(24, 96, L_), 256>>>(W2, w2h, w2l, FF_, D_);
    pe_kernel<<<S_, 256>>>(pe);
    embed_kernel<<<NT_, 256>>>(x, seg, tok, se, pe, h, sh);

    const dim3 gP(D_ / BN_, NT_ / BM_, 1);    // (6, 64)  N=768 GEMMs
    const dim3 gQKV(D_ / BN_, NT_ / BM_, 3);  // fused QKV
    const dim3 gF(FF_ / BN_, NT_ / BM_, 1);   // (24, 64) FF1

    for (int l = 0; l < L_; ++l) {
        const size_t wOff  = (size_t)l * D_ * D_;
        const size_t fOff1 = (size_t)l * D_ * FF_;
        const size_t fOff2 = (size_t)l * FF_ * D_;

        {   // QKV from fp16 h
            BOp oq = { wqh + wOff, wql + wOff, bq + l * D_, q,   nullptr };
            BOp ok = { wkh + wOff, wkl + wOff, bk + l * D_, k,   nullptr };
            BOp ov = { wvh + wOff, wvl + wOff, bv + l * D_, v,   nullptr };
            gemm_kernel<false><<<gQKV, GT_, GSMEM_>>>(sh, oq, ok, ov, D_, D_);
        }

        attn_fused_kernel<<<B_ * H_, 256>>>(q, k, v, x, sh);   // fp16 ctx

        {   // O projection from fp16 ctx
            BOp oo = { woh + wOff, wol + wOff, bo + l * D_, tmp, nullptr };
            gemm_kernel<false><<<gP, GT_, GSMEM_>>>(sh, oo, oo, oo, D_, D_);
        }
        resid_ln_kernel<<<NT_, 256>>>(tmp, h, lng + l * D_, lnb + l * D_, h1, sh);

        {   // FF1 (+GELU) from fp16 h1 -> fp16 ff (no fp32 output)
            BOp o1 = { w1h + fOff1, w1l + fOff1, b1 + l * FF_, nullptr, ah };
            gemm_kernel<true><<<gF, GT_, GSMEM_>>>(sh, o1, o1, o1, D_, FF_);
        }
        {   // FF2 from fp16 ff
            BOp o2 = { w2h + fOff2, w2l + fOff2, b2 + l * D_, tmp, nullptr };
            gemm_kernel<false><<<gP, GT_, GSMEM_>>>(ah, o2, o2, o2, FF_, D_);
        }

        float* dst = (l == L_ - 1) ? out : h;
        resid_ln_kernel<<<NT_, 256>>>(tmp, h1, lng + l * D_, lnb + l * D_, dst, sh);
    }
}

// round 13
// speedup vs baseline: 2.8519x; 1.5350x over previous
#include <cuda_runtime.h>
#include <cuda_fp16.h>
#include <math.h>
#include <stdint.h>

// ---------------------------------------------------------------------------
// BERT-base forward (B=128, S=64, D=768, H=12, L=12, FF=3072).
// GEMMs: mma.sync (HMMA) plain fp16 1-pass, fp32 accumulators.
//   (measured error chain: bf16-3pass 1.77e-5 -> fp16-2pass 3.42e-4 ->
//    fp16-1pass predicted ~5e-4, under the 1e-3 gate)
// 256 thr, 128x128x64 tiles, 2-stage cp.async, 2 CTAs/SM (32 KB/stage).
// Attention / LayerNorm / embedding: fp32 CUDA-core kernels.
// ---------------------------------------------------------------------------

#define B_    128
#define S_    64
#define D_    768
#define H_    12
#define DK_   64
#define FF_   3072
#define L_    12
#define NT_   (B_ * S_)          // 8192 tokens

// -------------------- scratch (device globals; no allocs) -------------------
__device__ float g_h   [NT_ * D_];
__device__ float g_h1  [NT_ * D_];
__device__ float g_q   [NT_ * D_];
__device__ float g_k   [NT_ * D_];
__device__ float g_v   [NT_ * D_];
__device__ float g_tmp [NT_ * D_];
__device__ float g_pe  [S_ * D_];

// fp16 activations: pairA (FF-sized, FF1 out), pairB (D-sized, h/ctx/h1)
__device__ __half g_ah[NT_ * FF_];
__device__ __half g_sh[NT_ * D_];

// fp16 transposed weights: [L][N][K] layout (K contiguous per row)
__device__ __half g_wq[L_ * D_ * D_];
__device__ __half g_wk[L_ * D_ * D_];
__device__ __half g_wv[L_ * D_ * D_];
__device__ __half g_wo[L_ * D_ * D_];
__device__ __half g_w1[L_ * FF_ * D_];   // [L][3072][768]
__device__ __half g_w2[L_ * D_ * FF_];   // [L][768][3072]

// -------------------- PTX helpers (all arch-agnostic, sm_80+) ---------------
__device__ __forceinline__ uint32_t smem_u32(const void* p) {
    uint32_t a;
    asm("{ .reg .u64 t; cvta.to.shared.u64 t, %1; cvt.u32.u64 %0, t; }"
        : "=r"(a) : "l"(p));
    return a;
}
__device__ __forceinline__ void cp16(uint32_t s, const void* g) {
    asm volatile("cp.async.cg.shared.global [%0], [%1], 16;" :: "r"(s), "l"(g) : "memory");
}
__device__ __forceinline__ void ldsm4(uint32_t& r0, uint32_t& r1, uint32_t& r2,
                                      uint32_t& r3, uint32_t a) {
    asm volatile("ldmatrix.sync.aligned.m8n8.x4.shared.b16 {%0,%1,%2,%3}, [%4];"
                 : "=r"(r0), "=r"(r1), "=r"(r2), "=r"(r3) : "r"(a));
}
__device__ __forceinline__ void mma16816(float* c, const uint32_t* a,
                                         uint32_t b0, uint32_t b1) {
    asm volatile("mma.sync.aligned.m16n8k16.row.col.f32.f16.f16.f32 "
                 "{%0,%1,%2,%3}, {%4,%5,%6,%7}, {%8,%9}, {%0,%1,%2,%3};"
                 : "+f"(c[0]), "+f"(c[1]), "+f"(c[2]), "+f"(c[3])
                 : "r"(a[0]), "r"(a[1]), "r"(a[2]), "r"(a[3]), "r"(b0), "r"(b1));
}

// -------------------- HMMA fp16 1-pass GEMM ---------------------------------
// C[8192, N] = A[8192, K] @ W[K, N] + bias (+GELU). A, W fp16; W transposed
// to Bt[N, K]. CTA tile 128x128, BK=64. Output fp32 (op.c) and/or fp16 (op.oh).
struct BOp { const __half* bt; const float* bias; float* c; __half* oh; };

#define GT_       256
#define BM_       128
#define BN_       128
#define BK_       64
#define TILE_B_   16384u       // 128 rows x 128 bytes
#define STAGE_B_  32768u       // A, B
#define GSMEM_    (2 * 32768)

template <bool GELU>
__global__ __launch_bounds__(GT_, 2)
void gemm_kernel(const __half* __restrict__ A,
                 BOp op0, BOp op1, BOp op2, int K, int N)
{
    extern __shared__ char smem[];
    const uint32_t sb = smem_u32(smem);
    const int tid = threadIdx.x, wid = tid >> 5, l = tid & 31;
    const int wm = wid & 1;          // 2 warps along M
    const int wn = wid >> 1;         // 4 warps along N
    const BOp op = (blockIdx.z == 0) ? op0 : ((blockIdx.z == 1) ? op1 : op2);
    const int m0 = blockIdx.y * BM_;
    const int n0 = blockIdx.x * BN_;

    // per-lane ldmatrix addressing components
    const uint32_t swz  = (uint32_t)((l & 7) << 4);
    const int aRow0     = wm * 64 + ((l >> 3) & 1) * 8 + (l & 7);
    const uint32_t aSel = (uint32_t)(((l >> 4) & 1) * 16);
    const int bRow0     = wn * 32 + ((l >> 4) & 1) * 8 + (l & 7);
    const uint32_t bSel = (uint32_t)(((l >> 3) & 1) * 16);

    float acc[4][4][4];
    #pragma unroll
    for (int i = 0; i < 4; ++i)
        #pragma unroll
        for (int j = 0; j < 4; ++j)
            #pragma unroll
            for (int e = 0; e < 4; ++e) acc[i][j][e] = 0.0f;

    const int nch = K / BK_;

    // ---- async prefetch of one stage (A|B tiles): 8 cp16/thread ----
    auto prefetch = [&](int c, int s) {
        const int kc = c * BK_;
        const uint32_t sbase = sb + (uint32_t)s * STAGE_B_;
        #pragma unroll 4
        for (int g = tid; g < 2048; g += GT_) {
            const int t   = g >> 10;                 // 0=A, 1=B
            const int idx = g & 1023;
            const int row = idx >> 3, seg = idx & 7;
            const uint32_t sa = sbase + (uint32_t)t * TILE_B_ + (uint32_t)row * 128
                              + (((uint32_t)(seg * 16)) ^ ((uint32_t)(row & 7) << 4));
            const __half* src;
            if (t == 0) src = A     + (size_t)(m0 + row) * K + kc + seg * 8;
            else        src = op.bt + (size_t)(n0 + row) * K + kc + seg * 8;
            cp16(sa, src);
        }
        asm volatile("cp.async.commit_group;" ::: "memory");
    };

    prefetch(0, 0);

    for (int c = 0; c < nch; ++c) {
        if (c + 1 < nch) {
            prefetch(c + 1, (c + 1) & 1);
            asm volatile("cp.async.wait_group 1;" ::: "memory");
        } else {
            asm volatile("cp.async.wait_group 0;" ::: "memory");
        }
        __syncthreads();

        const uint32_t sbase = sb + (uint32_t)(c & 1) * STAGE_B_;
        #pragma unroll
        for (int ks = 0; ks < 4; ++ks) {
            const uint32_t aCol = ((uint32_t)(ks * 32) + aSel) ^ swz;
            const uint32_t bCol = ((uint32_t)(ks * 32) + bSel) ^ swz;
            uint32_t a[4][4];
            #pragma unroll
            for (int mb = 0; mb < 4; ++mb)
                ldsm4(a[mb][0], a[mb][1], a[mb][2], a[mb][3],
                      sbase + (uint32_t)(aRow0 + mb * 16) * 128 + aCol);
            #pragma unroll
            for (int nb = 0; nb < 2; ++nb) {
                uint32_t b0, b1, b2, b3;
                ldsm4(b0, b1, b2, b3,
                      sbase + TILE_B_ + (uint32_t)(bRow0 + nb * 16) * 128 + bCol);
                #pragma unroll
                for (int mb = 0; mb < 4; ++mb) {
                    mma16816(acc[mb][nb * 2 + 0], a[mb], b0, b1);
                    mma16816(acc[mb][nb * 2 + 1], a[mb], b2, b3);
                }
            }
        }
        __syncthreads();
    }

    // ---- epilogue: bias (+GELU), fp32 and/or fp16 stores ----
    const int rbase = m0 + wm * 64 + (l >> 2);
    const int cbase = n0 + wn * 32 + (l & 3) * 2;
    #pragma unroll
    for (int mb = 0; mb < 4; ++mb) {
        #pragma unroll
        for (int nblk = 0; nblk < 4; ++nblk) {
            const int col = cbase + nblk * 8;
            const float bx = op.bias[col], by = op.bias[col + 1];
            float v[4] = { acc[mb][nblk][0] + bx, acc[mb][nblk][1] + by,
                           acc[mb][nblk][2] + bx, acc[mb][nblk][3] + by };
            if (GELU) {
                #pragma unroll
                for (int e = 0; e < 4; ++e)
                    v[e] = 0.5f * v[e] * (1.0f + erff(v[e] * 0.70710678118654752440f));
            }
            const int row = rbase + mb * 16;
            if (op.c) {
                float2 lo; lo.x = v[0]; lo.y = v[1];
                float2 hi; hi.x = v[2]; hi.y = v[3];
                *(float2*)(op.c + (size_t)row * N + col)       = lo;
                *(float2*)(op.c + (size_t)(row + 8) * N + col) = hi;
            }
            if (op.oh) {
                __half2 h0, h1;
                h0.x = __float2half_rn(v[0]);
                h0.y = __float2half_rn(v[1]);
                h1.x = __float2half_rn(v[2]);
                h1.y = __float2half_rn(v[3]);
                *(__half2*)(op.oh + (size_t)row * N + col)       = h0;
                *(__half2*)(op.oh + (size_t)(row + 8) * N + col) = h1;
            }
        }
    }
}

// -------------------- weight transpose -> fp16 ------------------------------
__global__ void wtrans_kernel(const float* __restrict__ W,
                              __half* __restrict__ th, int Kd, int Nd)
{
    __shared__ float t[32][33];
    const size_t lo_ = (size_t)blockIdx.z * Kd * Nd;
    const float* Wp = W + lo_;
    __half* thp = th + lo_;
    const int n0 = blockIdx.x * 32, k0 = blockIdx.y * 32;
    const int tx = threadIdx.x & 31, ty = threadIdx.x >> 5;

    #pragma unroll
    for (int j = 0; j < 32; j += 8)
        t[ty + j][tx] = Wp[(size_t)(k0 + ty + j) * Nd + n0 + tx];
    __syncthreads();
    #pragma unroll
    for (int j = 0; j < 32; j += 8)
        thp[(size_t)(n0 + ty + j) * Kd + k0 + tx] = __float2half_rn(t[tx][ty + j]);
}

// fused transpose for the four DxD weight families (one launch)
struct W4 { const float* w; __half* th; };
__global__ void wtrans4_kernel(W4 a, W4 b, W4 c, W4 d)
{
    __shared__ float t[32][33];
    const int which = blockIdx.z & 3;
    const int lyr   = blockIdx.z >> 2;
    const W4 s = (which == 0) ? a : (which == 1) ? b : (which == 2) ? c : d;
    const size_t lo_ = (size_t)lyr * D_ * D_;
    const float* Wp = s.w + lo_;
    __half* thp = s.th + lo_;
    const int n0 = blockIdx.x * 32, k0 = blockIdx.y * 32;
    const int tx = threadIdx.x & 31, ty = threadIdx.x >> 5;

    #pragma unroll
    for (int j = 0; j < 32; j += 8)
        t[ty + j][tx] = Wp[(size_t)(k0 + ty + j) * D_ + n0 + tx];
    __syncthreads();
    #pragma unroll
    for (int j = 0; j < 32; j += 8)
        thp[(size_t)(n0 + ty + j) * D_ + k0 + tx] = __float2half_rn(t[tx][ty + j]);
}

// -------------------- positional-encoding table -----------------------------
__global__ void pe_kernel(float* __restrict__ pe)
{
    const int s = blockIdx.x;
    for (int c = threadIdx.x; c < D_; c += blockDim.x) {
        const int j = c >> 1;
        const double e   = (double)(4 * j) / 768.0;
        const double inv = pow(10000.0, -e);
        const float  arg = (float)((double)s * inv);
        pe[s * D_ + c] = (c & 1) ? cosf(arg) : sinf(arg);
    }
}

// -------------------- embedding (fp32 + fp16) -------------------------------
__global__ void embed_kernel(const int* __restrict__ x, const int* __restrict__ seg,
                             const float* __restrict__ tok, const float* __restrict__ se,
                             const float* __restrict__ pe, float* __restrict__ h,
                             __half* __restrict__ sh)
{
    const int t   = blockIdx.x;
    const int tid = threadIdx.x;
    const int s   = t & (S_ - 1);
    const int xi  = x[t];
    const int si  = seg[t];
    const size_t base = (size_t)t * D_;
    #pragma unroll
    for (int u = 0; u < 3; ++u) {
        const int c = tid + u * 256;
        const float v = tok[(size_t)xi * D_ + c] + se[(size_t)si * D_ + c] + pe[s * D_ + c];
        h[base + c] = v;
        sh[base + c] = __float2half_rn(v);
    }
}

// -------------------- fused attention: scores+softmax+PV (emit fp16) --------
// grid = B*H (1536), block = 256. Smem reuse: Qs->P, Ks->V after score phase.
__global__ void attn_fused_kernel(const float* __restrict__ q, const float* __restrict__ k,
                                  const float* __restrict__ v, const int* __restrict__ x,
                                  __half* __restrict__ oh)
{
    __shared__ float Qs[S_ * 65];     // phase 1: Q      phase 2: P
    __shared__ float Ks[S_ * 65];     // phase 1: K      phase 2: V (flat 64-stride)
    __shared__ int   mk[S_];

    const int bh = blockIdx.x;
    const int b  = bh / H_;
    const int h  = bh % H_;
    const int tid = threadIdx.x;

    const float* qbase = q + (size_t)(b * S_) * D_ + h * DK_;
    const float* kbase = k + (size_t)(b * S_) * D_ + h * DK_;
    const float* vbase = v + (size_t)(b * S_) * D_ + h * DK_;

    for (int idx = tid; idx < S_ * DK_; idx += 256) {
        const int r = idx >> 6, d = idx & 63;
        Qs[r * 65 + d] = qbase[(size_t)r * D_ + d];
        Ks[r * 65 + d] = kbase[(size_t)r * D_ + d];
    }
    if (tid < S_) mk[tid] = x[b * S_ + tid];
    __syncthreads();

    const int row = tid >> 2;          // query row 0..63
    const int jc  = (tid & 3) * 16;    // key-col block

    float sc[16];
    #pragma unroll
    for (int jj = 0; jj < 16; ++jj) sc[jj] = 0.0f;

    for (int d = 0; d < DK_; ++d) {
        const float qv = Qs[row * 65 + d];
        #pragma unroll
        for (int jj = 0; jj < 16; ++jj)
            sc[jj] += qv * Ks[(jc + jj) * 65 + d];
    }

    float mx = -3.0e38f;
    #pragma unroll
    for (int jj = 0; jj < 16; ++jj) {
        const float val = (mk[jc + jj] > 0) ? sc[jj] * 0.125f : -1.0e9f;
        sc[jj] = val;
        mx = fmaxf(mx, val);
    }
    mx = fmaxf(mx, __shfl_xor_sync(0xffffffffu, mx, 1));
    mx = fmaxf(mx, __shfl_xor_sync(0xffffffffu, mx, 2));

    float sum = 0.0f;
    #pragma unroll
    for (int jj = 0; jj < 16; ++jj) {
        sc[jj] = expf(sc[jj] - mx);
        sum += sc[jj];
    }
    sum += __shfl_xor_sync(0xffffffffu, sum, 1);
    sum += __shfl_xor_sync(0xffffffffu, sum, 2);
    const float pinv = 1.0f / sum;

    __syncthreads();   // all Qs/Ks reads of phase 1 complete

    // write P into Qs, load V into Ks (flat, stride 64)
    #pragma unroll
    for (int jj = 0; jj < 16; ++jj) Qs[row * 65 + jc + jj] = sc[jj] * pinv;
    for (int idx = tid; idx < S_ * DK_; idx += 256)
        Ks[idx] = vbase[(size_t)(idx >> 6) * D_ + (idx & 63)];
    __syncthreads();

    // ctx = P @ V : thread owns (row, 16 headdims at d0)
    const int d0 = (tid & 3) * 16;
    float acc[16];
    #pragma unroll
    for (int dd = 0; dd < 16; ++dd) acc[dd] = 0.0f;

    for (int j = 0; j < S_; ++j) {
        const float p = Qs[row * 65 + j];
        #pragma unroll
        for (int dd = 0; dd < 16; ++dd)
            acc[dd] += p * Ks[j * DK_ + d0 + dd];
    }

    const size_t obase = (size_t)(b * S_ + row) * D_ + h * DK_ + d0;
    #pragma unroll
    for (int dd = 0; dd < 16; dd += 2) {
        __half2 hb;
        hb.x = __float2half_rn(acc[dd]);
        hb.y = __float2half_rn(acc[dd + 1]);
        *(__half2*)(oh + obase + dd) = hb;
    }
}

// -------------------- residual add + layernorm (fp32 + fp16) ----------------
__global__ void resid_ln_kernel(const float* __restrict__ a, const float* __restrict__ r,
                                const float* __restrict__ g, const float* __restrict__ be,
                                float* __restrict__ out, __half* __restrict__ oh)
{
    const int t   = blockIdx.x;
    const int tid = threadIdx.x;
    const size_t base = (size_t)t * D_;

    const float y0 = a[base + tid]       + r[base + tid];
    const float y1 = a[base + tid + 256] + r[base + tid + 256];
    const float y2 = a[base + tid + 512] + r[base + tid + 512];

    __shared__ float red[256];
    red[tid] = y0 + y1 + y2;
    __syncthreads();
    #pragma unroll
    for (int o = 128; o > 0; o >>= 1) {
        if (tid < o) red[tid] += red[tid + o];
        __syncthreads();
    }
    const float mu = red[0] * (1.0f / 768.0f);
    __syncthreads();

    const float d0 = y0 - mu, d1 = y1 - mu, d2 = y2 - mu;
    red[tid] = d0 * d0 + d1 * d1 + d2 * d2;
    __syncthreads();
    #pragma unroll
    for (int o = 128; o > 0; o >>= 1) {
        if (tid < o) red[tid] += red[tid + o];
        __syncthreads();
    }
    const float var = red[0] * (1.0f / 768.0f);
    const float inv = rsqrtf(var + 1e-5f);

    const float o0 = d0 * inv * g[tid]       + be[tid];
    const float o1 = d1 * inv * g[tid + 256] + be[tid + 256];
    const float o2 = d2 * inv * g[tid + 512] + be[tid + 512];
    out[base + tid]       = o0;
    out[base + tid + 256] = o1;
    out[base + tid + 512] = o2;
    oh[base + tid]        = __float2half_rn(o0);
    oh[base + tid + 256]  = __float2half_rn(o1);
    oh[base + tid + 512]  = __float2half_rn(o2);
}

// ---------------------------------------------------------------------------
extern "C" void kernel_launch(void* const* d_in, const int* in_sizes, int n_in,
                              void* d_out, int out_size)
{
    const int*   x    = (const int*)  d_in[0];
    const int*   seg  = (const int*)  d_in[1];
    const float* tok  = (const float*)d_in[2];
    const float* se   = (const float*)d_in[3];
    const float* Wq   = (const float*)d_in[4];
    const float* bq   = (const float*)d_in[5];
    const float* Wk   = (const float*)d_in[6];
    const float* bk   = (const float*)d_in[7];
    const float* Wv   = (const float*)d_in[8];
    const float* bv   = (const float*)d_in[9];
    const float* Wo   = (const float*)d_in[10];
    const float* bo   = (const float*)d_in[11];
    const float* lng  = (const float*)d_in[12];
    const float* lnb  = (const float*)d_in[13];
    const float* W1   = (const float*)d_in[14];
    const float* b1   = (const float*)d_in[15];
    const float* W2   = (const float*)d_in[16];
    const float* b2   = (const float*)d_in[17];
    float* out = (float*)d_out;

    float *h, *h1, *q, *k, *v, *tmp, *pe;
    __half *ah, *sh;
    __half *wq, *wk, *wv, *wo, *w1, *w2;
    cudaGetSymbolAddress((void**)&h,   g_h);
    cudaGetSymbolAddress((void**)&h1,  g_h1);
    cudaGetSymbolAddress((void**)&q,   g_q);
    cudaGetSymbolAddress((void**)&k,   g_k);
    cudaGetSymbolAddress((void**)&v,   g_v);
    cudaGetSymbolAddress((void**)&tmp, g_tmp);
    cudaGetSymbolAddress((void**)&pe,  g_pe);
    cudaGetSymbolAddress((void**)&ah,  g_ah);
    cudaGetSymbolAddress((void**)&sh,  g_sh);
    cudaGetSymbolAddress((void**)&wq,  g_wq);
    cudaGetSymbolAddress((void**)&wk,  g_wk);
    cudaGetSymbolAddress((void**)&wv,  g_wv);
    cudaGetSymbolAddress((void**)&wo,  g_wo);
    cudaGetSymbolAddress((void**)&w1,  g_w1);
    cudaGetSymbolAddress((void**)&w2,  g_w2);

    cudaFuncSetAttribute(gemm_kernel<false>, cudaFuncAttributeMaxDynamicSharedMemorySize, GSMEM_);
    cudaFuncSetAttribute(gemm_kernel<true >, cudaFuncAttributeMaxDynamicSharedMemorySize, GSMEM_);

    // ---- setup ----
    {
        W4 aq = { Wq, wq }, ak = { Wk, wk }, av = { Wv, wv }, ao = { Wo, wo };
        wtrans4_kernel<<<dim3(24, 24, 4 * L_), 256>>>(aq, ak, av, ao);
    }
    wtrans_kernel<<<dim3(96, 24, L_), 256>>>(W1, w1, D_, FF_);
    wtrans_kernel<<<dim3(24, 96, L_), 256>>>(W2, w2, FF_, D_);
    pe_kernel<<<S_, 256>>>(pe);
    embed_kernel<<<NT_, 256>>>(x, seg, tok, se, pe, h, sh);

    const dim3 gP(D_ / BN_, NT_ / BM_, 1);    // (6, 64)  N=768 GEMMs
    const dim3 gQKV(D_ / BN_, NT_ / BM_, 3);  // fused QKV
    const dim3 gF(FF_ / BN_, NT_ / BM_, 1);   // (24, 64) FF1

    for (int l = 0; l < L_; ++l) {
        const size_t wOff  = (size_t)l * D_ * D_;
        const size_t fOff1 = (size_t)l * D_ * FF_;
        const size_t fOff2 = (size_t)l * FF_ * D_;

        {   // QKV from fp16 h
            BOp oq = { wq + wOff, bq + l * D_, q,   nullptr };
            BOp ok = { wk + wOff, bk + l * D_, k,   nullptr };
            BOp ov = { wv + wOff, bv + l * D_, v,   nullptr };
            gemm_kernel<false><<<gQKV, GT_, GSMEM_>>>(sh, oq, ok, ov, D_, D_);
        }

        attn_fused_kernel<<<B_ * H_, 256>>>(q, k, v, x, sh);   // fp16 ctx

        {   // O projection from fp16 ctx
            BOp oo = { wo + wOff, bo + l * D_, tmp, nullptr };
            gemm_kernel<false><<<gP, GT_, GSMEM_>>>(sh, oo, oo, oo, D_, D_);
        }
        resid_ln_kernel<<<NT_, 256>>>(tmp, h, lng + l * D_, lnb + l * D_, h1, sh);

        {   // FF1 (+GELU) from fp16 h1 -> fp16 ff (no fp32 output)
            BOp o1 = { w1 + fOff1, b1 + l * FF_, nullptr, ah };
            gemm_kernel<true><<<gF, GT_, GSMEM_>>>(sh, o1, o1, o1, D_, FF_);
        }
        {   // FF2 from fp16 ff
            BOp o2 = { w2 + fOff2, b2 + l * D_, tmp, nullptr };
            gemm_kernel<false><<<gP, GT_, GSMEM_>>>(ah, o2, o2, o2, FF_, D_);
        }

        float* dst = (l == L_ - 1) ? out : h;
        resid_ln_kernel<<<NT_, 256>>>(tmp, h1, lng + l * D_, lnb + l * D_, dst, sh);
    }
}